// round 10
// baseline (speedup 1.0000x reference)
#include <cuda_runtime.h>
#include <math.h>

#define BSZ      64
#define DFEAT    196608            // 3*256*256
#define KCHUNK   128
#define CHUNK    (DFEAT / KCHUNK)  // 1536
#define TK       128
#define NTILE    (CHUNK / TK)      // 12
#define JSBLK    768
#define ADVN     16384
#define OUTER    30
#define INNER    200
#define L2E      1.4426950408889634f
#define EPS_GW   0.0005f
#define KSCALE   (L2E / EPS_GW)
#define LOGP2    (-6.0f)           // log2(1/64)
#define TH_IN    1e-4f             // inner exit: |d| in log2 units
#define TH_MK    8e-3f             // outer exit: |dMk| in z units (~0.6% rel in T)

// ---- device scratch ----
__device__ float g_part[2 * KCHUNK * 4096];
__device__ float g_c[2 * 4096];
__device__ float g_lse[2 * DFEAT];
__device__ float g_js[2 * JSBLK];
__device__ float g_adv;
__device__ float g_gw;

__device__ __forceinline__ float fex2(float x) {
    float r;
    asm("ex2.approx.ftz.f32 %0, %1;" : "=f"(r) : "f"(x));
    return r;
}
__device__ __forceinline__ float flg2(float x) {
    float r;
    asm("lg2.approx.f32 %0, %1;" : "=f"(r) : "f"(x));
    return r;
}
// Two independent 32-lane sums, interleaved to overlap shuffle latency.
__device__ __forceinline__ void warp_sum2(float& s0, float& s1) {
#pragma unroll
    for (int o = 16; o; o >>= 1) {
        float t0 = __shfl_xor_sync(0xffffffffu, s0, o);
        float t1 = __shfl_xor_sync(0xffffffffu, s1, o);
        s0 += t0;
        s1 += t1;
    }
}
__device__ __forceinline__ void warp_max2(float& s0, float& s1) {
#pragma unroll
    for (int o = 16; o; o >>= 1) {
        float t0 = __shfl_xor_sync(0xffffffffu, s0, o);
        float t1 = __shfl_xor_sync(0xffffffffu, s1, o);
        s0 = fmaxf(s0, t0);
        s1 = fmaxf(s1, t1);
    }
}

// ============================================================
// Kernel 1: Gram partials  G = X X^T  (64x64), K-chunked
// ============================================================
__global__ __launch_bounds__(256) void gram_kernel(const float* __restrict__ lr,
                                                   const float* __restrict__ sr) {
    __shared__ float tile2[TK][68];
    const float* X = blockIdx.y ? sr : lr;
    float* out = g_part + (blockIdx.y * KCHUNK + blockIdx.x) * 4096;

    int tid = threadIdx.x;
    int ty = tid >> 4, tx = tid & 15;
    float acc[4][4];
#pragma unroll
    for (int r = 0; r < 4; ++r)
#pragma unroll
        for (int c = 0; c < 4; ++c) acc[r][c] = 0.f;

    long k0base = (long)blockIdx.x * CHUNK;
    for (int t = 0; t < NTILE; ++t) {
        long k0 = k0base + (long)t * TK;
        for (int idx = tid; idx < 64 * TK; idx += 256) {
            int r = idx >> 7;
            int c = idx & 127;
            tile2[c][r] = X[(long)r * DFEAT + k0 + c];
        }
        __syncthreads();
#pragma unroll 4
        for (int k = 0; k < TK; ++k) {
            float4 av = *(const float4*)&tile2[k][4 * ty];
            float4 bv = *(const float4*)&tile2[k][4 * tx];
            acc[0][0] = fmaf(av.x, bv.x, acc[0][0]);
            acc[0][1] = fmaf(av.x, bv.y, acc[0][1]);
            acc[0][2] = fmaf(av.x, bv.z, acc[0][2]);
            acc[0][3] = fmaf(av.x, bv.w, acc[0][3]);
            acc[1][0] = fmaf(av.y, bv.x, acc[1][0]);
            acc[1][1] = fmaf(av.y, bv.y, acc[1][1]);
            acc[1][2] = fmaf(av.y, bv.z, acc[1][2]);
            acc[1][3] = fmaf(av.y, bv.w, acc[1][3]);
            acc[2][0] = fmaf(av.z, bv.x, acc[2][0]);
            acc[2][1] = fmaf(av.z, bv.y, acc[2][1]);
            acc[2][2] = fmaf(av.z, bv.z, acc[2][2]);
            acc[2][3] = fmaf(av.z, bv.w, acc[2][3]);
            acc[3][0] = fmaf(av.w, bv.x, acc[3][0]);
            acc[3][1] = fmaf(av.w, bv.y, acc[3][1]);
            acc[3][2] = fmaf(av.w, bv.z, acc[3][2]);
            acc[3][3] = fmaf(av.w, bv.w, acc[3][3]);
        }
        __syncthreads();
    }
#pragma unroll
    for (int r = 0; r < 4; ++r)
#pragma unroll
        for (int c = 0; c < 4; ++c)
            out[(4 * ty + r) * 64 + 4 * tx + c] = acc[r][c];
}

__global__ void gram_reduce_kernel() {
    int o = blockIdx.x * blockDim.x + threadIdx.x;  // 8192
    const float* p = g_part + (o >> 12) * (KCHUNK * 4096) + (o & 4095);
    float s = 0.f;
#pragma unroll 8
    for (int c = 0; c < KCHUNK; ++c) s += p[c * 4096];
    g_c[o] = s;
}

// ============================================================
// Kernel 2/3: JS divergence
// ============================================================
__global__ void js_lse_kernel(const float* __restrict__ sr,
                              const float* __restrict__ hr) {
    int pos = blockIdx.x * blockDim.x + threadIdx.x;
    const float* ps = sr + pos;
    const float* ph = hr + pos;
    float m1 = -1e30f, s1 = 0.f, m2 = -1e30f, s2 = 0.f;
#pragma unroll 4
    for (int b = 0; b < BSZ; ++b) {
        float v = ps[(long)b * DFEAT];
        float nm = fmaxf(m1, v);
        s1 = s1 * exp2f((m1 - nm) * L2E) + exp2f((v - nm) * L2E);
        m1 = nm;
        float w = ph[(long)b * DFEAT];
        float nw = fmaxf(m2, w);
        s2 = s2 * exp2f((m2 - nw) * L2E) + exp2f((w - nw) * L2E);
        m2 = nw;
    }
    g_lse[pos]         = m1 + __logf(s1);
    g_lse[DFEAT + pos] = m2 + __logf(s2);
}

__device__ __forceinline__ void block_sum2(float& v1, float& v2, float* sred,
                                           int tid, int nwarp) {
    int lane = tid & 31, warp = tid >> 5;
#pragma unroll
    for (int o = 16; o; o >>= 1) {
        v1 += __shfl_xor_sync(0xffffffffu, v1, o);
        v2 += __shfl_xor_sync(0xffffffffu, v2, o);
    }
    if (!lane) { sred[warp] = v1; sred[32 + warp] = v2; }
    __syncthreads();
    if (!tid) {
        float a = 0.f, b = 0.f;
        for (int w = 0; w < nwarp; ++w) { a += sred[w]; b += sred[32 + w]; }
        v1 = a; v2 = b;
    }
}

__global__ void js_kl_kernel(const float* __restrict__ sr,
                             const float* __restrict__ hr) {
    __shared__ float sred[64];
    int tid = threadIdx.x;
    int pos = blockIdx.x * blockDim.x + tid;
    float l1 = g_lse[pos], l2 = g_lse[DFEAT + pos];
    float acc1 = 0.f, acc2 = 0.f;
#pragma unroll 4
    for (int b = 0; b < BSZ; ++b) {
        float lx = sr[(long)b * DFEAT + pos] - l1;
        float ly = hr[(long)b * DFEAT + pos] - l2;
        float px = exp2f(lx * L2E);
        float py = exp2f(ly * L2E);
        float mm = 0.5f * (px + py);
        float lm = __logf(mm);
        acc1 += mm * (lm - lx);
        acc2 += mm * (lm - ly);
    }
    block_sum2(acc1, acc2, sred, tid, 8);
    if (!tid) {
        g_js[blockIdx.x]         = acc1;
        g_js[JSBLK + blockIdx.x] = acc2;
    }
}

__global__ void adv_kernel(const float* __restrict__ d) {
    __shared__ float sred[64];
    int tid = threadIdx.x;
    float s = 0.f, dummy = 0.f;
    for (int i = tid; i < ADVN; i += 256) {
        float x = d[i];
        s += fmaxf(-x, 0.f) + log1pf(__expf(-fabsf(x)));
    }
    block_sum2(s, dummy, sred, tid, 8);
    if (!tid) g_adv = s;
}

// ============================================================
// Kernel 5: persistent single-block entropic GW
// Log-domain Sinkhorn, register-resident Mk, shfl reductions,
// tolerance-based inner/outer early exits (recalibrated v2)
// ============================================================
#define P68 68
#define GW_SMEM_FLOATS (5 * 64 * P68 + 4 * 64 + 80)
#define GW_SMEM_BYTES  (GW_SMEM_FLOATS * 4 + 32)

__global__ __launch_bounds__(1024, 1) void gw_kernel() {
    extern __shared__ float sm[];
    float* c1  = sm;                 // 64*68
    float* c2  = c1 + 64 * P68;
    float* Tm  = c2 + 64 * P68;
    float* M1  = Tm + 64 * P68;
    float* Mk  = M1 + 64 * P68;      // row-major base-2 log kernel
    float* sa  = Mk + 64 * P68;      // potentials a (log2 units)
    float* sb  = sa + 64;
    float* r1  = sb + 64;
    float* r2  = r1 + 64;
    float* red = r2 + 64;            // 80 floats
    int*  cfl  = (int*)(red + 80);   // [0..2] inner flag rotation
    int*  ofl  = cfl + 3;            // [0..1] outer flag rotation

    int tid  = threadIdx.x;
    int lane = tid & 31, w = tid >> 5;
    int ii = tid >> 4, jq = (tid & 15) << 2;   // matmul mapping

    // ---- 1) load reduced grams ----
    for (int e = tid; e < 4096; e += 1024) {
        c1[(e >> 6) * P68 + (e & 63)] = g_c[e];
        c2[(e >> 6) * P68 + (e & 63)] = g_c[4096 + e];
    }
    __syncthreads();

    // ---- 2) distances + normalization ----
    if (tid < 64) r1[tid] = c1[tid * P68 + tid];
    else if (tid < 128) { int t = tid - 64; r2[t] = c2[t * P68 + t]; }
    __syncthreads();

    float lm1 = 0.f, lm2 = 0.f;
    for (int e = tid; e < 4096; e += 1024) {
        int i = e >> 6, j = e & 63;
        float d1 = sqrtf(fmaxf(r1[i] + r1[j] - 2.f * c1[i * P68 + j], 0.f));
        float d2 = sqrtf(fmaxf(r2[i] + r2[j] - 2.f * c2[i * P68 + j], 0.f));
        c1[i * P68 + j] = d1;
        c2[i * P68 + j] = d2;
        lm1 = fmaxf(lm1, d1);
        lm2 = fmaxf(lm2, d2);
    }
    warp_max2(lm1, lm2);
    if (!lane) { red[w] = lm1; red[32 + w] = lm2; }
    __syncthreads();
    if (!tid) {
        float a = red[0], b = red[32];
        for (int ww = 1; ww < 32; ++ww) { a = fmaxf(a, red[ww]); b = fmaxf(b, red[32 + ww]); }
        red[64] = 1.f / a;
        red[65] = 1.f / b;
        ofl[0] = 0; ofl[1] = 0;
    }
    __syncthreads();
    float inv1 = red[64], inv2 = red[65];
    for (int e = tid; e < 4096; e += 1024) {
        int i = e >> 6, j = e & 63;
        c1[i * P68 + j] *= inv1;
        c2[i * P68 + j] *= inv2;
        Tm[i * P68 + j] = 1.f / 4096.f;
    }
    __syncthreads();

    if (tid < 64) {
        float s = 0.f;
        for (int j = 0; j < 64; ++j) { float v = c1[tid * P68 + j]; s = fmaf(v, v, s); }
        r1[tid] = s * (1.f / 64.f);
    } else if (tid < 128) {
        int t = tid - 64;
        float s = 0.f;
        for (int j = 0; j < 64; ++j) { float v = c2[t * P68 + j]; s = fmaf(v, v, s); }
        r2[t] = s * (1.f / 64.f);
    }
    __syncthreads();

    // ---- 3) outer mirror-descent ----
    for (int outer = 0; outer < OUTER; ++outer) {
        // M1 = T @ c2
        {
            float a0 = 0.f, a1 = 0.f, a2 = 0.f, a3 = 0.f;
#pragma unroll 8
            for (int k = 0; k < 64; ++k) {
                float tv = Tm[ii * P68 + k];
                float4 bv = *(const float4*)(c2 + k * P68 + jq);
                a0 = fmaf(tv, bv.x, a0);
                a1 = fmaf(tv, bv.y, a1);
                a2 = fmaf(tv, bv.z, a2);
                a3 = fmaf(tv, bv.w, a3);
            }
            *(float4*)(M1 + ii * P68 + jq) = make_float4(a0, a1, a2, a3);
        }
        __syncthreads();
        // Mk = (2 c1@M1 - constC) * KSCALE; outer-diff flag
        {
            float p0 = 0.f, p1 = 0.f, p2 = 0.f, p3 = 0.f;
#pragma unroll 8
            for (int k = 0; k < 64; ++k) {
                float av = c1[ii * P68 + k];
                float4 mv = *(const float4*)(M1 + k * P68 + jq);
                p0 = fmaf(av, mv.x, p0);
                p1 = fmaf(av, mv.y, p1);
                p2 = fmaf(av, mv.z, p2);
                p3 = fmaf(av, mv.w, p3);
            }
            float ri = r1[ii];
            float v0 = (2.f * p0 - ri - r2[jq + 0]) * KSCALE;
            float v1 = (2.f * p1 - ri - r2[jq + 1]) * KSCALE;
            float v2 = (2.f * p2 - ri - r2[jq + 2]) * KSCALE;
            float v3 = (2.f * p3 - ri - r2[jq + 3]) * KSCALE;
            float4 old = *(const float4*)(Mk + ii * P68 + jq);
            float dd = fmaxf(fmaxf(fabsf(old.x - v0), fabsf(old.y - v1)),
                             fmaxf(fabsf(old.z - v2), fabsf(old.w - v3)));
            if (dd > TH_MK) ofl[outer & 1] = 1;
            *(float4*)(Mk + ii * P68 + jq) = make_float4(v0, v1, v2, v3);
        }
        if (tid < 64) sb[tid] = 0.f;
        if (!tid) { cfl[0] = 0; cfl[1] = 0; cfl[2] = 0; }
        __syncthreads();

        // Outer tolerance fixed point: remaining outers ~identity on T.
        if (outer > 0 && ofl[outer & 1] == 0) break;
        if (!tid) ofl[(outer + 1) & 1] = 0;

        // ---- register-resident Mk slices ----
        // rows {w, w+32} x cols {2l, 2l+1}
        float2 mr0 = *(const float2*)(Mk + w * P68 + 2 * lane);
        float2 mr1 = *(const float2*)(Mk + (w + 32) * P68 + 2 * lane);
        // cols {w, w+32} x rows {2l, 2l+1}
        float mc00 = Mk[(2 * lane) * P68 + w];
        float mc01 = Mk[(2 * lane + 1) * P68 + w];
        float mc10 = Mk[(2 * lane) * P68 + w + 32];
        float mc11 = Mk[(2 * lane + 1) * P68 + w + 32];

        // ---- a-update #1 (b = 0, max-stabilized) ----
        {
            float m0 = fmaxf(mr0.x, mr0.y);
            float m1 = fmaxf(mr1.x, mr1.y);
            warp_max2(m0, m1);
            float s0 = fex2(mr0.x - m0) + fex2(mr0.y - m0);
            float s1 = fex2(mr1.x - m1) + fex2(mr1.y - m1);
            warp_sum2(s0, s1);
            if ((lane & 15) == 0) {
                float mm = (lane < 16) ? m0 : m1;
                float ss = (lane < 16) ? s0 : s1;
                sa[(lane < 16) ? w : (w + 32)] = LOGP2 - (mm + flg2(ss));
            }
        }
        __syncthreads();

        // ---- pairs p = 1..199 {b,a} with windowed tolerance exit ----
#pragma unroll 1
        for (int p = 1; p < INNER; ++p) {
            int wp = ((p - 1) >> 2) % 3;
            {   // b-phase: columns w, w+32
                float b0 = sb[w], b1 = sb[w + 32];
                float2 av = *(const float2*)(sa + 2 * lane);
                float s0 = fex2(mc00 + av.x + b0) + fex2(mc01 + av.y + b0);
                float s1 = fex2(mc10 + av.x + b1) + fex2(mc11 + av.y + b1);
                warp_sum2(s0, s1);
                if ((lane & 15) == 0) {
                    float ss = (lane < 16) ? s0 : s1;
                    float bo = (lane < 16) ? b0 : b1;
                    float d = LOGP2 - flg2(ss);
                    sb[(lane < 16) ? w : (w + 32)] = bo + d;
                    if (fabsf(d) > TH_IN) cfl[wp] = 1;
                }
            }
            __syncthreads();
            {   // a-phase: rows w, w+32
                float a0 = sa[w], a1 = sa[w + 32];
                float2 bv = *(const float2*)(sb + 2 * lane);
                float s0 = fex2(mr0.x + a0 + bv.x) + fex2(mr0.y + a0 + bv.y);
                float s1 = fex2(mr1.x + a1 + bv.x) + fex2(mr1.y + a1 + bv.y);
                warp_sum2(s0, s1);
                if ((lane & 15) == 0) {
                    float ss = (lane < 16) ? s0 : s1;
                    float ao = (lane < 16) ? a0 : a1;
                    float d = LOGP2 - flg2(ss);
                    sa[(lane < 16) ? w : (w + 32)] = ao + d;
                    if (fabsf(d) > TH_IN) cfl[wp] = 1;
                }
            }
            __syncthreads();
            if ((p & 3) == 0) {
                int m = p >> 2;
                if (cfl[(m - 1) % 3] == 0) break;   // window converged
                if (!tid) cfl[(m + 1) % 3] = 0;
            }
        }

        {   // final b-phase (the 200th b-update)
            float b0 = sb[w], b1 = sb[w + 32];
            float2 av = *(const float2*)(sa + 2 * lane);
            float s0 = fex2(mc00 + av.x + b0) + fex2(mc01 + av.y + b0);
            float s1 = fex2(mc10 + av.x + b1) + fex2(mc11 + av.y + b1);
            warp_sum2(s0, s1);
            if ((lane & 15) == 0) {
                float ss = (lane < 16) ? s0 : s1;
                float bo = (lane < 16) ? b0 : b1;
                sb[(lane < 16) ? w : (w + 32)] = bo + (LOGP2 - flg2(ss));
            }
        }
        __syncthreads();

        // ---- T = 2^(a + Mk + b) from column registers ----
        {
            float b0 = sb[w], b1 = sb[w + 32];
            float2 av = *(const float2*)(sa + 2 * lane);
            Tm[(2 * lane) * P68 + w]          = fex2(mc00 + av.x + b0);
            Tm[(2 * lane + 1) * P68 + w]      = fex2(mc01 + av.y + b0);
            Tm[(2 * lane) * P68 + w + 32]     = fex2(mc10 + av.x + b1);
            Tm[(2 * lane + 1) * P68 + w + 32] = fex2(mc11 + av.y + b1);
        }
        __syncthreads();
    }

    // ---- 4) gw = sum(tens(T) * T) ----
    {
        float a0 = 0.f, a1 = 0.f, a2 = 0.f, a3 = 0.f;
#pragma unroll 8
        for (int k = 0; k < 64; ++k) {
            float tv = Tm[ii * P68 + k];
            float4 bv = *(const float4*)(c2 + k * P68 + jq);
            a0 = fmaf(tv, bv.x, a0);
            a1 = fmaf(tv, bv.y, a1);
            a2 = fmaf(tv, bv.z, a2);
            a3 = fmaf(tv, bv.w, a3);
        }
        *(float4*)(M1 + ii * P68 + jq) = make_float4(a0, a1, a2, a3);
    }
    __syncthreads();
    {
        float p0 = 0.f, p1 = 0.f, p2 = 0.f, p3 = 0.f;
#pragma unroll 8
        for (int k = 0; k < 64; ++k) {
            float av = c1[ii * P68 + k];
            float4 mv = *(const float4*)(M1 + k * P68 + jq);
            p0 = fmaf(av, mv.x, p0);
            p1 = fmaf(av, mv.y, p1);
            p2 = fmaf(av, mv.z, p2);
            p3 = fmaf(av, mv.w, p3);
        }
        float ri = r1[ii];
        float local =
            (ri + r2[jq + 0] - 2.f * p0) * Tm[ii * P68 + jq + 0] +
            (ri + r2[jq + 1] - 2.f * p1) * Tm[ii * P68 + jq + 1] +
            (ri + r2[jq + 2] - 2.f * p2) * Tm[ii * P68 + jq + 2] +
            (ri + r2[jq + 3] - 2.f * p3) * Tm[ii * P68 + jq + 3];
        float dummy = 0.f;
        warp_sum2(local, dummy);
        if (!lane) red[w] = local;
        __syncthreads();
        if (!tid) {
            float s = 0.f;
            for (int ww = 0; ww < 32; ++ww) s += red[ww];
            g_gw = s;
        }
    }
}

// ============================================================
// Kernel 6: final combine
// ============================================================
__global__ void final_kernel(float* __restrict__ out) {
    __shared__ float sred[64];
    int tid = threadIdx.x;
    float s1 = 0.f, s2 = 0.f;
    for (int i = tid; i < JSBLK; i += 256) {
        s1 += g_js[i];
        s2 += g_js[JSBLK + i];
    }
    block_sum2(s1, s2, sred, tid, 8);
    if (!tid) {
        float js  = 0.5f * (s1 + s2) * (1.f / 64.f);
        float adv = g_adv * (1.f / (float)ADVN);
        float gw  = g_gw;
        float mx = fmaxf(gw, fmaxf(js, adv));
        float w0 = expf((gw - mx) * 10.f);
        float w1 = expf((js - mx) * 10.f);
        float w2 = expf((adv - mx) * 10.f);
        float den = w0 + w1 + w2;
        out[0] = (gw * w0 + js * w1 + adv * w2) / den;
    }
}

// ============================================================
extern "C" void kernel_launch(void* const* d_in, const int* in_sizes, int n_in,
                              void* d_out, int out_size) {
    const float* big[3] = {nullptr, nullptr, nullptr};
    const float* df = nullptr;
    int nb = 0;
    for (int i = 0; i < n_in; ++i) {
        if (in_sizes[i] == ADVN) df = (const float*)d_in[i];
        else if (nb < 3) big[nb++] = (const float*)d_in[i];
    }
    const float* lr = big[0];
    const float* sr = big[1];
    const float* hr = big[2];
    float* out = (float*)d_out;
    (void)out_size;

    cudaFuncSetAttribute(gw_kernel, cudaFuncAttributeMaxDynamicSharedMemorySize,
                         GW_SMEM_BYTES);

    gram_kernel<<<dim3(KCHUNK, 2), 256>>>(lr, sr);
    gram_reduce_kernel<<<32, 256>>>();
    js_lse_kernel<<<JSBLK, 256>>>(sr, hr);
    js_kl_kernel<<<JSBLK, 256>>>(sr, hr);
    adv_kernel<<<1, 256>>>(df);
    gw_kernel<<<1, 1024, GW_SMEM_BYTES>>>();
    final_kernel<<<1, 256>>>(out);
}

// round 12
// speedup vs baseline: 1.0418x; 1.0418x over previous
#include <cuda_runtime.h>
#include <math.h>

#define BSZ      64
#define DFEAT    196608            // 3*256*256
#define KCHUNK   128
#define CHUNK    (DFEAT / KCHUNK)  // 1536
#define TK       128
#define NTILE    (CHUNK / TK)      // 12
#define JSBLK    768
#define ADVN     16384
#define OUTER    30
#define INNER    200
#define L2E      1.4426950408889634f
#define EPS_GW   0.0005f
#define KSCALE   (L2E / EPS_GW)
#define LOGP2    (-6.0f)           // log2(1/64)
#define TH_IN    1e-4f             // inner exit: |d| in log2 units
#define TH_MK    8e-3f             // outer exit: |dMk| in z units
#define SOR_W    1.7f              // over-relaxation factor (same fixed point)
#define SOR_P0   4                 // plain updates for p <= SOR_P0 (overflow safety)

// ---- device scratch ----
__device__ float g_part[2 * KCHUNK * 4096];
__device__ float g_c[2 * 4096];
__device__ float g_lse[2 * DFEAT];
__device__ float g_js[2 * JSBLK];
__device__ float g_adv;
__device__ float g_gw;

__device__ __forceinline__ float fex2(float x) {
    float r;
    asm("ex2.approx.ftz.f32 %0, %1;" : "=f"(r) : "f"(x));
    return r;
}
__device__ __forceinline__ float flg2(float x) {
    float r;
    asm("lg2.approx.f32 %0, %1;" : "=f"(r) : "f"(x));
    return r;
}
// Two independent 32-lane sums, interleaved to overlap shuffle latency.
__device__ __forceinline__ void warp_sum2(float& s0, float& s1) {
#pragma unroll
    for (int o = 16; o; o >>= 1) {
        float t0 = __shfl_xor_sync(0xffffffffu, s0, o);
        float t1 = __shfl_xor_sync(0xffffffffu, s1, o);
        s0 += t0;
        s1 += t1;
    }
}
__device__ __forceinline__ void warp_max2(float& s0, float& s1) {
#pragma unroll
    for (int o = 16; o; o >>= 1) {
        float t0 = __shfl_xor_sync(0xffffffffu, s0, o);
        float t1 = __shfl_xor_sync(0xffffffffu, s1, o);
        s0 = fmaxf(s0, t0);
        s1 = fmaxf(s1, t1);
    }
}

// ============================================================
// Kernel 1: Gram partials  G = X X^T  (64x64), K-chunked
// ============================================================
__global__ __launch_bounds__(256) void gram_kernel(const float* __restrict__ lr,
                                                   const float* __restrict__ sr) {
    __shared__ float tile2[TK][68];
    const float* X = blockIdx.y ? sr : lr;
    float* out = g_part + (blockIdx.y * KCHUNK + blockIdx.x) * 4096;

    int tid = threadIdx.x;
    int ty = tid >> 4, tx = tid & 15;
    float acc[4][4];
#pragma unroll
    for (int r = 0; r < 4; ++r)
#pragma unroll
        for (int c = 0; c < 4; ++c) acc[r][c] = 0.f;

    long k0base = (long)blockIdx.x * CHUNK;
    for (int t = 0; t < NTILE; ++t) {
        long k0 = k0base + (long)t * TK;
        for (int idx = tid; idx < 64 * TK; idx += 256) {
            int r = idx >> 7;
            int c = idx & 127;
            tile2[c][r] = X[(long)r * DFEAT + k0 + c];
        }
        __syncthreads();
#pragma unroll 4
        for (int k = 0; k < TK; ++k) {
            float4 av = *(const float4*)&tile2[k][4 * ty];
            float4 bv = *(const float4*)&tile2[k][4 * tx];
            acc[0][0] = fmaf(av.x, bv.x, acc[0][0]);
            acc[0][1] = fmaf(av.x, bv.y, acc[0][1]);
            acc[0][2] = fmaf(av.x, bv.z, acc[0][2]);
            acc[0][3] = fmaf(av.x, bv.w, acc[0][3]);
            acc[1][0] = fmaf(av.y, bv.x, acc[1][0]);
            acc[1][1] = fmaf(av.y, bv.y, acc[1][1]);
            acc[1][2] = fmaf(av.y, bv.z, acc[1][2]);
            acc[1][3] = fmaf(av.y, bv.w, acc[1][3]);
            acc[2][0] = fmaf(av.z, bv.x, acc[2][0]);
            acc[2][1] = fmaf(av.z, bv.y, acc[2][1]);
            acc[2][2] = fmaf(av.z, bv.z, acc[2][2]);
            acc[2][3] = fmaf(av.z, bv.w, acc[2][3]);
            acc[3][0] = fmaf(av.w, bv.x, acc[3][0]);
            acc[3][1] = fmaf(av.w, bv.y, acc[3][1]);
            acc[3][2] = fmaf(av.w, bv.z, acc[3][2]);
            acc[3][3] = fmaf(av.w, bv.w, acc[3][3]);
        }
        __syncthreads();
    }
#pragma unroll
    for (int r = 0; r < 4; ++r)
#pragma unroll
        for (int c = 0; c < 4; ++c)
            out[(4 * ty + r) * 64 + 4 * tx + c] = acc[r][c];
}

__global__ void gram_reduce_kernel() {
    int o = blockIdx.x * blockDim.x + threadIdx.x;  // 8192
    const float* p = g_part + (o >> 12) * (KCHUNK * 4096) + (o & 4095);
    float s = 0.f;
#pragma unroll 8
    for (int c = 0; c < KCHUNK; ++c) s += p[c * 4096];
    g_c[o] = s;
}

// ============================================================
// Kernel 2/3: JS divergence
// ============================================================
__global__ void js_lse_kernel(const float* __restrict__ sr,
                              const float* __restrict__ hr) {
    int pos = blockIdx.x * blockDim.x + threadIdx.x;
    const float* ps = sr + pos;
    const float* ph = hr + pos;
    float m1 = -1e30f, s1 = 0.f, m2 = -1e30f, s2 = 0.f;
#pragma unroll 4
    for (int b = 0; b < BSZ; ++b) {
        float v = ps[(long)b * DFEAT];
        float nm = fmaxf(m1, v);
        s1 = s1 * exp2f((m1 - nm) * L2E) + exp2f((v - nm) * L2E);
        m1 = nm;
        float w = ph[(long)b * DFEAT];
        float nw = fmaxf(m2, w);
        s2 = s2 * exp2f((m2 - nw) * L2E) + exp2f((w - nw) * L2E);
        m2 = nw;
    }
    g_lse[pos]         = m1 + __logf(s1);
    g_lse[DFEAT + pos] = m2 + __logf(s2);
}

__device__ __forceinline__ void block_sum2(float& v1, float& v2, float* sred,
                                           int tid, int nwarp) {
    int lane = tid & 31, warp = tid >> 5;
#pragma unroll
    for (int o = 16; o; o >>= 1) {
        v1 += __shfl_xor_sync(0xffffffffu, v1, o);
        v2 += __shfl_xor_sync(0xffffffffu, v2, o);
    }
    if (!lane) { sred[warp] = v1; sred[32 + warp] = v2; }
    __syncthreads();
    if (!tid) {
        float a = 0.f, b = 0.f;
        for (int w = 0; w < nwarp; ++w) { a += sred[w]; b += sred[32 + w]; }
        v1 = a; v2 = b;
    }
}

__global__ void js_kl_kernel(const float* __restrict__ sr,
                             const float* __restrict__ hr) {
    __shared__ float sred[64];
    int tid = threadIdx.x;
    int pos = blockIdx.x * blockDim.x + tid;
    float l1 = g_lse[pos], l2 = g_lse[DFEAT + pos];
    float acc1 = 0.f, acc2 = 0.f;
#pragma unroll 4
    for (int b = 0; b < BSZ; ++b) {
        float lx = sr[(long)b * DFEAT + pos] - l1;
        float ly = hr[(long)b * DFEAT + pos] - l2;
        float px = exp2f(lx * L2E);
        float py = exp2f(ly * L2E);
        float mm = 0.5f * (px + py);
        float lm = __logf(mm);
        acc1 += mm * (lm - lx);
        acc2 += mm * (lm - ly);
    }
    block_sum2(acc1, acc2, sred, tid, 8);
    if (!tid) {
        g_js[blockIdx.x]         = acc1;
        g_js[JSBLK + blockIdx.x] = acc2;
    }
}

__global__ void adv_kernel(const float* __restrict__ d) {
    __shared__ float sred[64];
    int tid = threadIdx.x;
    float s = 0.f, dummy = 0.f;
    for (int i = tid; i < ADVN; i += 256) {
        float x = d[i];
        s += fmaxf(-x, 0.f) + log1pf(__expf(-fabsf(x)));
    }
    block_sum2(s, dummy, sred, tid, 8);
    if (!tid) g_adv = s;
}

// ============================================================
// Kernel 5: persistent single-block entropic GW
// Log-domain Sinkhorn, register-resident Mk, shfl reductions,
// SOR-accelerated updates + tolerance early exits
// ============================================================
#define P68 68
#define GW_SMEM_FLOATS (5 * 64 * P68 + 4 * 64 + 80)
#define GW_SMEM_BYTES  (GW_SMEM_FLOATS * 4 + 32)

__global__ __launch_bounds__(1024, 1) void gw_kernel() {
    extern __shared__ float sm[];
    float* c1  = sm;                 // 64*68
    float* c2  = c1 + 64 * P68;
    float* Tm  = c2 + 64 * P68;
    float* M1  = Tm + 64 * P68;
    float* Mk  = M1 + 64 * P68;      // row-major base-2 log kernel
    float* sa  = Mk + 64 * P68;      // potentials a (log2 units)
    float* sb  = sa + 64;
    float* r1  = sb + 64;
    float* r2  = r1 + 64;
    float* red = r2 + 64;            // 80 floats
    int*  cfl  = (int*)(red + 80);   // [0..2] inner flag rotation
    int*  ofl  = cfl + 3;            // [0..1] outer flag rotation

    int tid  = threadIdx.x;
    int lane = tid & 31, w = tid >> 5;
    int ii = tid >> 4, jq = (tid & 15) << 2;   // matmul mapping

    // ---- 1) load reduced grams ----
    for (int e = tid; e < 4096; e += 1024) {
        c1[(e >> 6) * P68 + (e & 63)] = g_c[e];
        c2[(e >> 6) * P68 + (e & 63)] = g_c[4096 + e];
    }
    __syncthreads();

    // ---- 2) distances + normalization ----
    if (tid < 64) r1[tid] = c1[tid * P68 + tid];
    else if (tid < 128) { int t = tid - 64; r2[t] = c2[t * P68 + t]; }
    __syncthreads();

    float lm1 = 0.f, lm2 = 0.f;
    for (int e = tid; e < 4096; e += 1024) {
        int i = e >> 6, j = e & 63;
        float d1 = sqrtf(fmaxf(r1[i] + r1[j] - 2.f * c1[i * P68 + j], 0.f));
        float d2 = sqrtf(fmaxf(r2[i] + r2[j] - 2.f * c2[i * P68 + j], 0.f));
        c1[i * P68 + j] = d1;
        c2[i * P68 + j] = d2;
        lm1 = fmaxf(lm1, d1);
        lm2 = fmaxf(lm2, d2);
    }
    warp_max2(lm1, lm2);
    if (!lane) { red[w] = lm1; red[32 + w] = lm2; }
    __syncthreads();
    if (!tid) {
        float a = red[0], b = red[32];
        for (int ww = 1; ww < 32; ++ww) { a = fmaxf(a, red[ww]); b = fmaxf(b, red[32 + ww]); }
        red[64] = 1.f / a;
        red[65] = 1.f / b;
        ofl[0] = 0; ofl[1] = 0;
    }
    __syncthreads();
    float inv1 = red[64], inv2 = red[65];
    for (int e = tid; e < 4096; e += 1024) {
        int i = e >> 6, j = e & 63;
        c1[i * P68 + j] *= inv1;
        c2[i * P68 + j] *= inv2;
        Tm[i * P68 + j] = 1.f / 4096.f;
    }
    __syncthreads();

    if (tid < 64) {
        float s = 0.f;
        for (int j = 0; j < 64; ++j) { float v = c1[tid * P68 + j]; s = fmaf(v, v, s); }
        r1[tid] = s * (1.f / 64.f);
    } else if (tid < 128) {
        int t = tid - 64;
        float s = 0.f;
        for (int j = 0; j < 64; ++j) { float v = c2[t * P68 + j]; s = fmaf(v, v, s); }
        r2[t] = s * (1.f / 64.f);
    }
    __syncthreads();

    // ---- 3) outer mirror-descent ----
    for (int outer = 0; outer < OUTER; ++outer) {
        // M1 = T @ c2
        {
            float a0 = 0.f, a1 = 0.f, a2 = 0.f, a3 = 0.f;
#pragma unroll 8
            for (int k = 0; k < 64; ++k) {
                float tv = Tm[ii * P68 + k];
                float4 bv = *(const float4*)(c2 + k * P68 + jq);
                a0 = fmaf(tv, bv.x, a0);
                a1 = fmaf(tv, bv.y, a1);
                a2 = fmaf(tv, bv.z, a2);
                a3 = fmaf(tv, bv.w, a3);
            }
            *(float4*)(M1 + ii * P68 + jq) = make_float4(a0, a1, a2, a3);
        }
        __syncthreads();
        // Mk = (2 c1@M1 - constC) * KSCALE; outer-diff flag
        {
            float p0 = 0.f, p1 = 0.f, p2 = 0.f, p3 = 0.f;
#pragma unroll 8
            for (int k = 0; k < 64; ++k) {
                float av = c1[ii * P68 + k];
                float4 mv = *(const float4*)(M1 + k * P68 + jq);
                p0 = fmaf(av, mv.x, p0);
                p1 = fmaf(av, mv.y, p1);
                p2 = fmaf(av, mv.z, p2);
                p3 = fmaf(av, mv.w, p3);
            }
            float ri = r1[ii];
            float v0 = (2.f * p0 - ri - r2[jq + 0]) * KSCALE;
            float v1 = (2.f * p1 - ri - r2[jq + 1]) * KSCALE;
            float v2 = (2.f * p2 - ri - r2[jq + 2]) * KSCALE;
            float v3 = (2.f * p3 - ri - r2[jq + 3]) * KSCALE;
            float4 old = *(const float4*)(Mk + ii * P68 + jq);
            float dd = fmaxf(fmaxf(fabsf(old.x - v0), fabsf(old.y - v1)),
                             fmaxf(fabsf(old.z - v2), fabsf(old.w - v3)));
            if (dd > TH_MK) ofl[outer & 1] = 1;
            *(float4*)(Mk + ii * P68 + jq) = make_float4(v0, v1, v2, v3);
        }
        if (tid < 64) sb[tid] = 0.f;
        if (!tid) { cfl[0] = 0; cfl[1] = 0; cfl[2] = 0; }
        __syncthreads();

        // Outer tolerance fixed point: remaining outers ~identity on T.
        if (outer > 0 && ofl[outer & 1] == 0) break;
        if (!tid) ofl[(outer + 1) & 1] = 0;

        // ---- register-resident Mk slices ----
        // rows {w, w+32} x cols {2l, 2l+1}
        float2 mr0 = *(const float2*)(Mk + w * P68 + 2 * lane);
        float2 mr1 = *(const float2*)(Mk + (w + 32) * P68 + 2 * lane);
        // cols {w, w+32} x rows {2l, 2l+1}
        float mc00 = Mk[(2 * lane) * P68 + w];
        float mc01 = Mk[(2 * lane + 1) * P68 + w];
        float mc10 = Mk[(2 * lane) * P68 + w + 32];
        float mc11 = Mk[(2 * lane + 1) * P68 + w + 32];

        // ---- a-update #1 (b = 0, max-stabilized) ----
        {
            float m0 = fmaxf(mr0.x, mr0.y);
            float m1 = fmaxf(mr1.x, mr1.y);
            warp_max2(m0, m1);
            float s0 = fex2(mr0.x - m0) + fex2(mr0.y - m0);
            float s1 = fex2(mr1.x - m1) + fex2(mr1.y - m1);
            warp_sum2(s0, s1);
            if ((lane & 15) == 0) {
                float mm = (lane < 16) ? m0 : m1;
                float ss = (lane < 16) ? s0 : s1;
                sa[(lane < 16) ? w : (w + 32)] = LOGP2 - (mm + flg2(ss));
            }
        }
        __syncthreads();

        // ---- pairs p = 1..199 {b,a}: SOR updates + windowed exit ----
#pragma unroll 1
        for (int p = 1; p < INNER; ++p) {
            int wp = ((p - 1) >> 2) % 3;
            float om = (p > SOR_P0) ? SOR_W : 1.0f;
            {   // b-phase: columns w, w+32
                float b0 = sb[w], b1 = sb[w + 32];
                float2 av = *(const float2*)(sa + 2 * lane);
                float s0 = fex2(mc00 + av.x + b0) + fex2(mc01 + av.y + b0);
                float s1 = fex2(mc10 + av.x + b1) + fex2(mc11 + av.y + b1);
                warp_sum2(s0, s1);
                if ((lane & 15) == 0) {
                    float ss = (lane < 16) ? s0 : s1;
                    float bo = (lane < 16) ? b0 : b1;
                    float d = LOGP2 - flg2(ss);
                    sb[(lane < 16) ? w : (w + 32)] = bo + om * d;
                    if (fabsf(d) > TH_IN) cfl[wp] = 1;
                }
            }
            __syncthreads();
            {   // a-phase: rows w, w+32
                float a0 = sa[w], a1 = sa[w + 32];
                float2 bv = *(const float2*)(sb + 2 * lane);
                float s0 = fex2(mr0.x + a0 + bv.x) + fex2(mr0.y + a0 + bv.y);
                float s1 = fex2(mr1.x + a1 + bv.x) + fex2(mr1.y + a1 + bv.y);
                warp_sum2(s0, s1);
                if ((lane & 15) == 0) {
                    float ss = (lane < 16) ? s0 : s1;
                    float ao = (lane < 16) ? a0 : a1;
                    float d = LOGP2 - flg2(ss);
                    sa[(lane < 16) ? w : (w + 32)] = ao + om * d;
                    if (fabsf(d) > TH_IN) cfl[wp] = 1;
                }
            }
            __syncthreads();
            if ((p & 3) == 0) {
                int m = p >> 2;
                if (cfl[(m - 1) % 3] == 0) break;   // window converged
                if (!tid) cfl[(m + 1) % 3] = 0;
            }
        }

        {   // final b-phase: plain update (exact column marginal, like ref)
            float b0 = sb[w], b1 = sb[w + 32];
            float2 av = *(const float2*)(sa + 2 * lane);
            float s0 = fex2(mc00 + av.x + b0) + fex2(mc01 + av.y + b0);
            float s1 = fex2(mc10 + av.x + b1) + fex2(mc11 + av.y + b1);
            warp_sum2(s0, s1);
            if ((lane & 15) == 0) {
                float ss = (lane < 16) ? s0 : s1;
                float bo = (lane < 16) ? b0 : b1;
                sb[(lane < 16) ? w : (w + 32)] = bo + (LOGP2 - flg2(ss));
            }
        }
        __syncthreads();

        // ---- T = 2^(a + Mk + b) from column registers ----
        {
            float b0 = sb[w], b1 = sb[w + 32];
            float2 av = *(const float2*)(sa + 2 * lane);
            Tm[(2 * lane) * P68 + w]          = fex2(mc00 + av.x + b0);
            Tm[(2 * lane + 1) * P68 + w]      = fex2(mc01 + av.y + b0);
            Tm[(2 * lane) * P68 + w + 32]     = fex2(mc10 + av.x + b1);
            Tm[(2 * lane + 1) * P68 + w + 32] = fex2(mc11 + av.y + b1);
        }
        __syncthreads();
    }

    // ---- 4) gw = sum(tens(T) * T) ----
    {
        float a0 = 0.f, a1 = 0.f, a2 = 0.f, a3 = 0.f;
#pragma unroll 8
        for (int k = 0; k < 64; ++k) {
            float tv = Tm[ii * P68 + k];
            float4 bv = *(const float4*)(c2 + k * P68 + jq);
            a0 = fmaf(tv, bv.x, a0);
            a1 = fmaf(tv, bv.y, a1);
            a2 = fmaf(tv, bv.z, a2);
            a3 = fmaf(tv, bv.w, a3);
        }
        *(float4*)(M1 + ii * P68 + jq) = make_float4(a0, a1, a2, a3);
    }
    __syncthreads();
    {
        float p0 = 0.f, p1 = 0.f, p2 = 0.f, p3 = 0.f;
#pragma unroll 8
        for (int k = 0; k < 64; ++k) {
            float av = c1[ii * P68 + k];
            float4 mv = *(const float4*)(M1 + k * P68 + jq);
            p0 = fmaf(av, mv.x, p0);
            p1 = fmaf(av, mv.y, p1);
            p2 = fmaf(av, mv.z, p2);
            p3 = fmaf(av, mv.w, p3);
        }
        float ri = r1[ii];
        float local =
            (ri + r2[jq + 0] - 2.f * p0) * Tm[ii * P68 + jq + 0] +
            (ri + r2[jq + 1] - 2.f * p1) * Tm[ii * P68 + jq + 1] +
            (ri + r2[jq + 2] - 2.f * p2) * Tm[ii * P68 + jq + 2] +
            (ri + r2[jq + 3] - 2.f * p3) * Tm[ii * P68 + jq + 3];
        float dummy = 0.f;
        warp_sum2(local, dummy);
        if (!lane) red[w] = local;
        __syncthreads();
        if (!tid) {
            float s = 0.f;
            for (int ww = 0; ww < 32; ++ww) s += red[ww];
            g_gw = s;
        }
    }
}

// ============================================================
// Kernel 6: final combine
// ============================================================
__global__ void final_kernel(float* __restrict__ out) {
    __shared__ float sred[64];
    int tid = threadIdx.x;
    float s1 = 0.f, s2 = 0.f;
    for (int i = tid; i < JSBLK; i += 256) {
        s1 += g_js[i];
        s2 += g_js[JSBLK + i];
    }
    block_sum2(s1, s2, sred, tid, 8);
    if (!tid) {
        float js  = 0.5f * (s1 + s2) * (1.f / 64.f);
        float adv = g_adv * (1.f / (float)ADVN);
        float gw  = g_gw;
        float mx = fmaxf(gw, fmaxf(js, adv));
        float w0 = expf((gw - mx) * 10.f);
        float w1 = expf((js - mx) * 10.f);
        float w2 = expf((adv - mx) * 10.f);
        float den = w0 + w1 + w2;
        out[0] = (gw * w0 + js * w1 + adv * w2) / den;
    }
}

// ============================================================
extern "C" void kernel_launch(void* const* d_in, const int* in_sizes, int n_in,
                              void* d_out, int out_size) {
    const float* big[3] = {nullptr, nullptr, nullptr};
    const float* df = nullptr;
    int nb = 0;
    for (int i = 0; i < n_in; ++i) {
        if (in_sizes[i] == ADVN) df = (const float*)d_in[i];
        else if (nb < 3) big[nb++] = (const float*)d_in[i];
    }
    const float* lr = big[0];
    const float* sr = big[1];
    const float* hr = big[2];
    float* out = (float*)d_out;
    (void)out_size;

    cudaFuncSetAttribute(gw_kernel, cudaFuncAttributeMaxDynamicSharedMemorySize,
                         GW_SMEM_BYTES);

    gram_kernel<<<dim3(KCHUNK, 2), 256>>>(lr, sr);
    gram_reduce_kernel<<<32, 256>>>();
    js_lse_kernel<<<JSBLK, 256>>>(sr, hr);
    js_kl_kernel<<<JSBLK, 256>>>(sr, hr);
    adv_kernel<<<1, 256>>>(df);
    gw_kernel<<<1, 1024, GW_SMEM_BYTES>>>();
    final_kernel<<<1, 256>>>(out);
}

// round 13
// speedup vs baseline: 1.0505x; 1.0084x over previous
#include <cuda_runtime.h>
#include <math.h>

#define BSZ      64
#define DFEAT    196608            // 3*256*256
#define KCHUNK   128
#define CHUNK    (DFEAT / KCHUNK)  // 1536
#define TK       128
#define NTILE    (CHUNK / TK)      // 12
#define JSBLK    768
#define ADVN     16384
#define OUTER    30
#define INNER    200
#define L2E      1.4426950408889634f
#define EPS_GW   0.0005f
#define KSCALE   (L2E / EPS_GW)
#define LOGP2    (-6.0f)           // log2(1/64)
#define TH_IN    1e-4f             // inner exit: |d| in log2 units
#define TH_MK    8e-3f             // outer exit: |dMk| in z units

// ---- device scratch ----
__device__ float g_part[2 * KCHUNK * 4096];
__device__ float g_c[2 * 4096];
__device__ float g_lse[2 * DFEAT];
__device__ float g_js[2 * JSBLK];
__device__ float g_adv;
__device__ float g_gw;

__device__ __forceinline__ float fex2(float x) {
    float r;
    asm("ex2.approx.ftz.f32 %0, %1;" : "=f"(r) : "f"(x));
    return r;
}
__device__ __forceinline__ float flg2(float x) {
    float r;
    asm("lg2.approx.f32 %0, %1;" : "=f"(r) : "f"(x));
    return r;
}
// Two independent 32-lane sums, interleaved to overlap shuffle latency.
__device__ __forceinline__ void warp_sum2(float& s0, float& s1) {
#pragma unroll
    for (int o = 16; o; o >>= 1) {
        float t0 = __shfl_xor_sync(0xffffffffu, s0, o);
        float t1 = __shfl_xor_sync(0xffffffffu, s1, o);
        s0 += t0;
        s1 += t1;
    }
}
__device__ __forceinline__ void warp_max2(float& s0, float& s1) {
#pragma unroll
    for (int o = 16; o; o >>= 1) {
        float t0 = __shfl_xor_sync(0xffffffffu, s0, o);
        float t1 = __shfl_xor_sync(0xffffffffu, s1, o);
        s0 = fmaxf(s0, t0);
        s1 = fmaxf(s1, t1);
    }
}

// ============================================================
// Kernel 1: Gram partials  G = X X^T  (64x64), K-chunked
// ============================================================
__global__ __launch_bounds__(256) void gram_kernel(const float* __restrict__ lr,
                                                   const float* __restrict__ sr) {
    __shared__ float tile2[TK][68];
    const float* X = blockIdx.y ? sr : lr;
    float* out = g_part + (blockIdx.y * KCHUNK + blockIdx.x) * 4096;

    int tid = threadIdx.x;
    int ty = tid >> 4, tx = tid & 15;
    float acc[4][4];
#pragma unroll
    for (int r = 0; r < 4; ++r)
#pragma unroll
        for (int c = 0; c < 4; ++c) acc[r][c] = 0.f;

    long k0base = (long)blockIdx.x * CHUNK;
    for (int t = 0; t < NTILE; ++t) {
        long k0 = k0base + (long)t * TK;
        for (int idx = tid; idx < 64 * TK; idx += 256) {
            int r = idx >> 7;
            int c = idx & 127;
            tile2[c][r] = X[(long)r * DFEAT + k0 + c];
        }
        __syncthreads();
#pragma unroll 4
        for (int k = 0; k < TK; ++k) {
            float4 av = *(const float4*)&tile2[k][4 * ty];
            float4 bv = *(const float4*)&tile2[k][4 * tx];
            acc[0][0] = fmaf(av.x, bv.x, acc[0][0]);
            acc[0][1] = fmaf(av.x, bv.y, acc[0][1]);
            acc[0][2] = fmaf(av.x, bv.z, acc[0][2]);
            acc[0][3] = fmaf(av.x, bv.w, acc[0][3]);
            acc[1][0] = fmaf(av.y, bv.x, acc[1][0]);
            acc[1][1] = fmaf(av.y, bv.y, acc[1][1]);
            acc[1][2] = fmaf(av.y, bv.z, acc[1][2]);
            acc[1][3] = fmaf(av.y, bv.w, acc[1][3]);
            acc[2][0] = fmaf(av.z, bv.x, acc[2][0]);
            acc[2][1] = fmaf(av.z, bv.y, acc[2][1]);
            acc[2][2] = fmaf(av.z, bv.z, acc[2][2]);
            acc[2][3] = fmaf(av.z, bv.w, acc[2][3]);
            acc[3][0] = fmaf(av.w, bv.x, acc[3][0]);
            acc[3][1] = fmaf(av.w, bv.y, acc[3][1]);
            acc[3][2] = fmaf(av.w, bv.z, acc[3][2]);
            acc[3][3] = fmaf(av.w, bv.w, acc[3][3]);
        }
        __syncthreads();
    }
#pragma unroll
    for (int r = 0; r < 4; ++r)
#pragma unroll
        for (int c = 0; c < 4; ++c)
            out[(4 * ty + r) * 64 + 4 * tx + c] = acc[r][c];
}

__global__ void gram_reduce_kernel() {
    int o = blockIdx.x * blockDim.x + threadIdx.x;  // 8192
    const float* p = g_part + (o >> 12) * (KCHUNK * 4096) + (o & 4095);
    float s = 0.f;
#pragma unroll 8
    for (int c = 0; c < KCHUNK; ++c) s += p[c * 4096];
    g_c[o] = s;
}

// ============================================================
// Kernel 2/3: JS divergence
// ============================================================
__global__ void js_lse_kernel(const float* __restrict__ sr,
                              const float* __restrict__ hr) {
    int pos = blockIdx.x * blockDim.x + threadIdx.x;
    const float* ps = sr + pos;
    const float* ph = hr + pos;
    float m1 = -1e30f, s1 = 0.f, m2 = -1e30f, s2 = 0.f;
#pragma unroll 4
    for (int b = 0; b < BSZ; ++b) {
        float v = ps[(long)b * DFEAT];
        float nm = fmaxf(m1, v);
        s1 = s1 * exp2f((m1 - nm) * L2E) + exp2f((v - nm) * L2E);
        m1 = nm;
        float w = ph[(long)b * DFEAT];
        float nw = fmaxf(m2, w);
        s2 = s2 * exp2f((m2 - nw) * L2E) + exp2f((w - nw) * L2E);
        m2 = nw;
    }
    g_lse[pos]         = m1 + __logf(s1);
    g_lse[DFEAT + pos] = m2 + __logf(s2);
}

__device__ __forceinline__ void block_sum2(float& v1, float& v2, float* sred,
                                           int tid, int nwarp) {
    int lane = tid & 31, warp = tid >> 5;
#pragma unroll
    for (int o = 16; o; o >>= 1) {
        v1 += __shfl_xor_sync(0xffffffffu, v1, o);
        v2 += __shfl_xor_sync(0xffffffffu, v2, o);
    }
    if (!lane) { sred[warp] = v1; sred[32 + warp] = v2; }
    __syncthreads();
    if (!tid) {
        float a = 0.f, b = 0.f;
        for (int w = 0; w < nwarp; ++w) { a += sred[w]; b += sred[32 + w]; }
        v1 = a; v2 = b;
    }
}

__global__ void js_kl_kernel(const float* __restrict__ sr,
                             const float* __restrict__ hr) {
    __shared__ float sred[64];
    int tid = threadIdx.x;
    int pos = blockIdx.x * blockDim.x + tid;
    float l1 = g_lse[pos], l2 = g_lse[DFEAT + pos];
    float acc1 = 0.f, acc2 = 0.f;
#pragma unroll 4
    for (int b = 0; b < BSZ; ++b) {
        float lx = sr[(long)b * DFEAT + pos] - l1;
        float ly = hr[(long)b * DFEAT + pos] - l2;
        float px = exp2f(lx * L2E);
        float py = exp2f(ly * L2E);
        float mm = 0.5f * (px + py);
        float lm = __logf(mm);
        acc1 += mm * (lm - lx);
        acc2 += mm * (lm - ly);
    }
    block_sum2(acc1, acc2, sred, tid, 8);
    if (!tid) {
        g_js[blockIdx.x]         = acc1;
        g_js[JSBLK + blockIdx.x] = acc2;
    }
}

__global__ void adv_kernel(const float* __restrict__ d) {
    __shared__ float sred[64];
    int tid = threadIdx.x;
    float s = 0.f, dummy = 0.f;
    for (int i = tid; i < ADVN; i += 256) {
        float x = d[i];
        s += fmaxf(-x, 0.f) + log1pf(__expf(-fabsf(x)));
    }
    block_sum2(s, dummy, sred, tid, 8);
    if (!tid) g_adv = s;
}

// ============================================================
// Kernel 5: persistent single-block entropic GW
// Log-domain Sinkhorn, register-resident Mk, shfl reductions,
// warm-started potentials across outers + tolerance exits
// ============================================================
#define P68 68
#define GW_SMEM_FLOATS (5 * 64 * P68 + 4 * 64 + 80)
#define GW_SMEM_BYTES  (GW_SMEM_FLOATS * 4 + 32)

__global__ __launch_bounds__(1024, 1) void gw_kernel() {
    extern __shared__ float sm[];
    float* c1  = sm;                 // 64*68
    float* c2  = c1 + 64 * P68;
    float* Tm  = c2 + 64 * P68;
    float* M1  = Tm + 64 * P68;
    float* Mk  = M1 + 64 * P68;      // row-major base-2 log kernel
    float* sa  = Mk + 64 * P68;      // potentials a (log2 units)
    float* sb  = sa + 64;
    float* r1  = sb + 64;
    float* r2  = r1 + 64;
    float* red = r2 + 64;            // 80 floats
    int*  cfl  = (int*)(red + 80);   // [0..2] inner flag rotation
    int*  ofl  = cfl + 3;            // [0..1] outer flag rotation

    int tid  = threadIdx.x;
    int lane = tid & 31, w = tid >> 5;
    int ii = tid >> 4, jq = (tid & 15) << 2;   // matmul mapping

    // ---- 1) load reduced grams ----
    for (int e = tid; e < 4096; e += 1024) {
        c1[(e >> 6) * P68 + (e & 63)] = g_c[e];
        c2[(e >> 6) * P68 + (e & 63)] = g_c[4096 + e];
    }
    __syncthreads();

    // ---- 2) distances + normalization ----
    if (tid < 64) r1[tid] = c1[tid * P68 + tid];
    else if (tid < 128) { int t = tid - 64; r2[t] = c2[t * P68 + t]; }
    __syncthreads();

    float lm1 = 0.f, lm2 = 0.f;
    for (int e = tid; e < 4096; e += 1024) {
        int i = e >> 6, j = e & 63;
        float d1 = sqrtf(fmaxf(r1[i] + r1[j] - 2.f * c1[i * P68 + j], 0.f));
        float d2 = sqrtf(fmaxf(r2[i] + r2[j] - 2.f * c2[i * P68 + j], 0.f));
        c1[i * P68 + j] = d1;
        c2[i * P68 + j] = d2;
        lm1 = fmaxf(lm1, d1);
        lm2 = fmaxf(lm2, d2);
    }
    warp_max2(lm1, lm2);
    if (!lane) { red[w] = lm1; red[32 + w] = lm2; }
    __syncthreads();
    if (!tid) {
        float a = red[0], b = red[32];
        for (int ww = 1; ww < 32; ++ww) { a = fmaxf(a, red[ww]); b = fmaxf(b, red[32 + ww]); }
        red[64] = 1.f / a;
        red[65] = 1.f / b;
        ofl[0] = 0; ofl[1] = 0;
    }
    __syncthreads();
    float inv1 = red[64], inv2 = red[65];
    for (int e = tid; e < 4096; e += 1024) {
        int i = e >> 6, j = e & 63;
        c1[i * P68 + j] *= inv1;
        c2[i * P68 + j] *= inv2;
        Tm[i * P68 + j] = 1.f / 4096.f;
    }
    __syncthreads();

    if (tid < 64) {
        float s = 0.f;
        for (int j = 0; j < 64; ++j) { float v = c1[tid * P68 + j]; s = fmaf(v, v, s); }
        r1[tid] = s * (1.f / 64.f);
    } else if (tid < 128) {
        int t = tid - 64;
        float s = 0.f;
        for (int j = 0; j < 64; ++j) { float v = c2[t * P68 + j]; s = fmaf(v, v, s); }
        r2[t] = s * (1.f / 64.f);
    } else if (tid < 192) {
        sb[tid - 128] = 0.f;        // warm-start seed for outer 0
    }
    __syncthreads();

    // ---- 3) outer mirror-descent (warm-started potentials) ----
    for (int outer = 0; outer < OUTER; ++outer) {
        // M1 = T @ c2
        {
            float a0 = 0.f, a1 = 0.f, a2 = 0.f, a3 = 0.f;
#pragma unroll 8
            for (int k = 0; k < 64; ++k) {
                float tv = Tm[ii * P68 + k];
                float4 bv = *(const float4*)(c2 + k * P68 + jq);
                a0 = fmaf(tv, bv.x, a0);
                a1 = fmaf(tv, bv.y, a1);
                a2 = fmaf(tv, bv.z, a2);
                a3 = fmaf(tv, bv.w, a3);
            }
            *(float4*)(M1 + ii * P68 + jq) = make_float4(a0, a1, a2, a3);
        }
        __syncthreads();
        // Mk = (2 c1@M1 - constC) * KSCALE; outer-diff flag
        {
            float p0 = 0.f, p1 = 0.f, p2 = 0.f, p3 = 0.f;
#pragma unroll 8
            for (int k = 0; k < 64; ++k) {
                float av = c1[ii * P68 + k];
                float4 mv = *(const float4*)(M1 + k * P68 + jq);
                p0 = fmaf(av, mv.x, p0);
                p1 = fmaf(av, mv.y, p1);
                p2 = fmaf(av, mv.z, p2);
                p3 = fmaf(av, mv.w, p3);
            }
            float ri = r1[ii];
            float v0 = (2.f * p0 - ri - r2[jq + 0]) * KSCALE;
            float v1 = (2.f * p1 - ri - r2[jq + 1]) * KSCALE;
            float v2 = (2.f * p2 - ri - r2[jq + 2]) * KSCALE;
            float v3 = (2.f * p3 - ri - r2[jq + 3]) * KSCALE;
            float4 old = *(const float4*)(Mk + ii * P68 + jq);
            float dd = fmaxf(fmaxf(fabsf(old.x - v0), fabsf(old.y - v1)),
                             fmaxf(fabsf(old.z - v2), fabsf(old.w - v3)));
            if (dd > TH_MK) ofl[outer & 1] = 1;
            *(float4*)(Mk + ii * P68 + jq) = make_float4(v0, v1, v2, v3);
        }
        if (!tid) { cfl[0] = 0; cfl[1] = 0; cfl[2] = 0; }
        __syncthreads();

        // Outer tolerance fixed point: remaining outers ~identity on T.
        if (outer > 0 && ofl[outer & 1] == 0) break;
        if (!tid) ofl[(outer + 1) & 1] = 0;

        // ---- register-resident Mk slices ----
        // rows {w, w+32} x cols {2l, 2l+1}
        float2 mr0 = *(const float2*)(Mk + w * P68 + 2 * lane);
        float2 mr1 = *(const float2*)(Mk + (w + 32) * P68 + 2 * lane);
        // cols {w, w+32} x rows {2l, 2l+1}
        float mc00 = Mk[(2 * lane) * P68 + w];
        float mc01 = Mk[(2 * lane + 1) * P68 + w];
        float mc10 = Mk[(2 * lane) * P68 + w + 32];
        float mc11 = Mk[(2 * lane + 1) * P68 + w + 32];

        // ---- a-update #1: max-stabilized over (Mk + b_warm) ----
        // Absorbs arbitrary Mk jumps between outers (no overflow);
        // afterwards z = Mk + a + b <= -6 as before.
        {
            float2 bv = *(const float2*)(sb + 2 * lane);
            float x0 = mr0.x + bv.x, x1 = mr0.y + bv.y;
            float y0 = mr1.x + bv.x, y1 = mr1.y + bv.y;
            float m0 = fmaxf(x0, x1);
            float m1 = fmaxf(y0, y1);
            warp_max2(m0, m1);
            float s0 = fex2(x0 - m0) + fex2(x1 - m0);
            float s1 = fex2(y0 - m1) + fex2(y1 - m1);
            warp_sum2(s0, s1);
            if ((lane & 15) == 0) {
                float mm = (lane < 16) ? m0 : m1;
                float ss = (lane < 16) ? s0 : s1;
                sa[(lane < 16) ? w : (w + 32)] = LOGP2 - (mm + flg2(ss));
            }
        }
        __syncthreads();

        // ---- pairs p = 1..199 {b,a} with windowed tolerance exit ----
#pragma unroll 1
        for (int p = 1; p < INNER; ++p) {
            int wp = ((p - 1) >> 2) % 3;
            {   // b-phase: columns w, w+32
                float b0 = sb[w], b1 = sb[w + 32];
                float2 av = *(const float2*)(sa + 2 * lane);
                float s0 = fex2(mc00 + av.x + b0) + fex2(mc01 + av.y + b0);
                float s1 = fex2(mc10 + av.x + b1) + fex2(mc11 + av.y + b1);
                warp_sum2(s0, s1);
                if ((lane & 15) == 0) {
                    float ss = (lane < 16) ? s0 : s1;
                    float bo = (lane < 16) ? b0 : b1;
                    float d = LOGP2 - flg2(ss);
                    sb[(lane < 16) ? w : (w + 32)] = bo + d;
                    if (fabsf(d) > TH_IN) cfl[wp] = 1;
                }
            }
            __syncthreads();
            {   // a-phase: rows w, w+32
                float a0 = sa[w], a1 = sa[w + 32];
                float2 bv = *(const float2*)(sb + 2 * lane);
                float s0 = fex2(mr0.x + a0 + bv.x) + fex2(mr0.y + a0 + bv.y);
                float s1 = fex2(mr1.x + a1 + bv.x) + fex2(mr1.y + a1 + bv.y);
                warp_sum2(s0, s1);
                if ((lane & 15) == 0) {
                    float ss = (lane < 16) ? s0 : s1;
                    float ao = (lane < 16) ? a0 : a1;
                    float d = LOGP2 - flg2(ss);
                    sa[(lane < 16) ? w : (w + 32)] = ao + d;
                    if (fabsf(d) > TH_IN) cfl[wp] = 1;
                }
            }
            __syncthreads();
            if ((p & 3) == 0) {
                int m = p >> 2;
                if (cfl[(m - 1) % 3] == 0) break;   // window converged
                if (!tid) cfl[(m + 1) % 3] = 0;
            }
        }

        {   // final b-phase (exact column marginal, like ref)
            float b0 = sb[w], b1 = sb[w + 32];
            float2 av = *(const float2*)(sa + 2 * lane);
            float s0 = fex2(mc00 + av.x + b0) + fex2(mc01 + av.y + b0);
            float s1 = fex2(mc10 + av.x + b1) + fex2(mc11 + av.y + b1);
            warp_sum2(s0, s1);
            if ((lane & 15) == 0) {
                float ss = (lane < 16) ? s0 : s1;
                float bo = (lane < 16) ? b0 : b1;
                sb[(lane < 16) ? w : (w + 32)] = bo + (LOGP2 - flg2(ss));
            }
        }
        __syncthreads();

        // ---- T = 2^(a + Mk + b) from column registers ----
        {
            float b0 = sb[w], b1 = sb[w + 32];
            float2 av = *(const float2*)(sa + 2 * lane);
            Tm[(2 * lane) * P68 + w]          = fex2(mc00 + av.x + b0);
            Tm[(2 * lane + 1) * P68 + w]      = fex2(mc01 + av.y + b0);
            Tm[(2 * lane) * P68 + w + 32]     = fex2(mc10 + av.x + b1);
            Tm[(2 * lane + 1) * P68 + w + 32] = fex2(mc11 + av.y + b1);
        }
        __syncthreads();
    }

    // ---- 4) gw = sum(tens(T) * T) ----
    {
        float a0 = 0.f, a1 = 0.f, a2 = 0.f, a3 = 0.f;
#pragma unroll 8
        for (int k = 0; k < 64; ++k) {
            float tv = Tm[ii * P68 + k];
            float4 bv = *(const float4*)(c2 + k * P68 + jq);
            a0 = fmaf(tv, bv.x, a0);
            a1 = fmaf(tv, bv.y, a1);
            a2 = fmaf(tv, bv.z, a2);
            a3 = fmaf(tv, bv.w, a3);
        }
        *(float4*)(M1 + ii * P68 + jq) = make_float4(a0, a1, a2, a3);
    }
    __syncthreads();
    {
        float p0 = 0.f, p1 = 0.f, p2 = 0.f, p3 = 0.f;
#pragma unroll 8
        for (int k = 0; k < 64; ++k) {
            float av = c1[ii * P68 + k];
            float4 mv = *(const float4*)(M1 + k * P68 + jq);
            p0 = fmaf(av, mv.x, p0);
            p1 = fmaf(av, mv.y, p1);
            p2 = fmaf(av, mv.z, p2);
            p3 = fmaf(av, mv.w, p3);
        }
        float ri = r1[ii];
        float local =
            (ri + r2[jq + 0] - 2.f * p0) * Tm[ii * P68 + jq + 0] +
            (ri + r2[jq + 1] - 2.f * p1) * Tm[ii * P68 + jq + 1] +
            (ri + r2[jq + 2] - 2.f * p2) * Tm[ii * P68 + jq + 2] +
            (ri + r2[jq + 3] - 2.f * p3) * Tm[ii * P68 + jq + 3];
        float dummy = 0.f;
        warp_sum2(local, dummy);
        if (!lane) red[w] = local;
        __syncthreads();
        if (!tid) {
            float s = 0.f;
            for (int ww = 0; ww < 32; ++ww) s += red[ww];
            g_gw = s;
        }
    }
}

// ============================================================
// Kernel 6: final combine
// ============================================================
__global__ void final_kernel(float* __restrict__ out) {
    __shared__ float sred[64];
    int tid = threadIdx.x;
    float s1 = 0.f, s2 = 0.f;
    for (int i = tid; i < JSBLK; i += 256) {
        s1 += g_js[i];
        s2 += g_js[JSBLK + i];
    }
    block_sum2(s1, s2, sred, tid, 8);
    if (!tid) {
        float js  = 0.5f * (s1 + s2) * (1.f / 64.f);
        float adv = g_adv * (1.f / (float)ADVN);
        float gw  = g_gw;
        float mx = fmaxf(gw, fmaxf(js, adv));
        float w0 = expf((gw - mx) * 10.f);
        float w1 = expf((js - mx) * 10.f);
        float w2 = expf((adv - mx) * 10.f);
        float den = w0 + w1 + w2;
        out[0] = (gw * w0 + js * w1 + adv * w2) / den;
    }
}

// ============================================================
extern "C" void kernel_launch(void* const* d_in, const int* in_sizes, int n_in,
                              void* d_out, int out_size) {
    const float* big[3] = {nullptr, nullptr, nullptr};
    const float* df = nullptr;
    int nb = 0;
    for (int i = 0; i < n_in; ++i) {
        if (in_sizes[i] == ADVN) df = (const float*)d_in[i];
        else if (nb < 3) big[nb++] = (const float*)d_in[i];
    }
    const float* lr = big[0];
    const float* sr = big[1];
    const float* hr = big[2];
    float* out = (float*)d_out;
    (void)out_size;

    cudaFuncSetAttribute(gw_kernel, cudaFuncAttributeMaxDynamicSharedMemorySize,
                         GW_SMEM_BYTES);

    gram_kernel<<<dim3(KCHUNK, 2), 256>>>(lr, sr);
    gram_reduce_kernel<<<32, 256>>>();
    js_lse_kernel<<<JSBLK, 256>>>(sr, hr);
    js_kl_kernel<<<JSBLK, 256>>>(sr, hr);
    adv_kernel<<<1, 256>>>(df);
    gw_kernel<<<1, 1024, GW_SMEM_BYTES>>>();
    final_kernel<<<1, 256>>>(out);
}

// round 14
// speedup vs baseline: 1.1200x; 1.0661x over previous
#include <cuda_runtime.h>
#include <math.h>

#define BSZ      64
#define DFEAT    196608            // 3*256*256
#define KCHUNK   128
#define CHUNK    (DFEAT / KCHUNK)  // 1536
#define TK       128
#define NTILE    (CHUNK / TK)      // 12
#define JSBLK    768
#define ADVN     16384
#define OUTER    30
#define INNER    200
#define L2E      1.4426950408889634f
#define EPS_GW   0.0005f
#define KSCALE   (L2E / EPS_GW)
#define LOGP2    (-6.0f)           // log2(1/64)
#define TH_IN    1e-4f             // inner exit: |d| in log2 units
#define TH_MK    8e-3f             // outer exit: |dMk| in z units
#define FXS      31.0f             // fixed-point scale exponent for redux sums

// ---- device scratch ----
__device__ float g_part[2 * KCHUNK * 4096];
__device__ float g_c[2 * 4096];
__device__ float g_lse[2 * DFEAT];
__device__ float g_js[2 * JSBLK];
__device__ float g_adv;
__device__ float g_gw;

__device__ __forceinline__ float fex2(float x) {
    float r;
    asm("ex2.approx.ftz.f32 %0, %1;" : "=f"(r) : "f"(x));
    return r;
}
__device__ __forceinline__ float flg2(float x) {
    float r;
    asm("lg2.approx.f32 %0, %1;" : "=f"(r) : "f"(x));
    return r;
}
__device__ __forceinline__ unsigned f2u_rni(float x) {
    unsigned r;
    asm("cvt.rni.u32.f32 %0, %1;" : "=r"(r) : "f"(x));
    return r;
}
__device__ __forceinline__ float u2f(unsigned x) {
    float r;
    asm("cvt.rn.f32.u32 %0, %1;" : "=f"(r) : "r"(x));
    return r;
}
__device__ __forceinline__ unsigned redux_add_u32(unsigned v) {
    unsigned r;
    asm("redux.sync.add.u32 %0, %1, 0xffffffff;" : "=r"(r) : "r"(v));
    return r;
}
// Two independent 32-lane sums, interleaved to overlap shuffle latency.
__device__ __forceinline__ void warp_sum2(float& s0, float& s1) {
#pragma unroll
    for (int o = 16; o; o >>= 1) {
        float t0 = __shfl_xor_sync(0xffffffffu, s0, o);
        float t1 = __shfl_xor_sync(0xffffffffu, s1, o);
        s0 += t0;
        s1 += t1;
    }
}
__device__ __forceinline__ void warp_max2(float& s0, float& s1) {
#pragma unroll
    for (int o = 16; o; o >>= 1) {
        float t0 = __shfl_xor_sync(0xffffffffu, s0, o);
        float t1 = __shfl_xor_sync(0xffffffffu, s1, o);
        s0 = fmaxf(s0, t0);
        s1 = fmaxf(s1, t1);
    }
}

// ============================================================
// Kernel 1: Gram partials  G = X X^T  (64x64), K-chunked
// ============================================================
__global__ __launch_bounds__(256) void gram_kernel(const float* __restrict__ lr,
                                                   const float* __restrict__ sr) {
    __shared__ float tile2[TK][68];
    const float* X = blockIdx.y ? sr : lr;
    float* out = g_part + (blockIdx.y * KCHUNK + blockIdx.x) * 4096;

    int tid = threadIdx.x;
    int ty = tid >> 4, tx = tid & 15;
    float acc[4][4];
#pragma unroll
    for (int r = 0; r < 4; ++r)
#pragma unroll
        for (int c = 0; c < 4; ++c) acc[r][c] = 0.f;

    long k0base = (long)blockIdx.x * CHUNK;
    for (int t = 0; t < NTILE; ++t) {
        long k0 = k0base + (long)t * TK;
        for (int idx = tid; idx < 64 * TK; idx += 256) {
            int r = idx >> 7;
            int c = idx & 127;
            tile2[c][r] = X[(long)r * DFEAT + k0 + c];
        }
        __syncthreads();
#pragma unroll 4
        for (int k = 0; k < TK; ++k) {
            float4 av = *(const float4*)&tile2[k][4 * ty];
            float4 bv = *(const float4*)&tile2[k][4 * tx];
            acc[0][0] = fmaf(av.x, bv.x, acc[0][0]);
            acc[0][1] = fmaf(av.x, bv.y, acc[0][1]);
            acc[0][2] = fmaf(av.x, bv.z, acc[0][2]);
            acc[0][3] = fmaf(av.x, bv.w, acc[0][3]);
            acc[1][0] = fmaf(av.y, bv.x, acc[1][0]);
            acc[1][1] = fmaf(av.y, bv.y, acc[1][1]);
            acc[1][2] = fmaf(av.y, bv.z, acc[1][2]);
            acc[1][3] = fmaf(av.y, bv.w, acc[1][3]);
            acc[2][0] = fmaf(av.z, bv.x, acc[2][0]);
            acc[2][1] = fmaf(av.z, bv.y, acc[2][1]);
            acc[2][2] = fmaf(av.z, bv.z, acc[2][2]);
            acc[2][3] = fmaf(av.z, bv.w, acc[2][3]);
            acc[3][0] = fmaf(av.w, bv.x, acc[3][0]);
            acc[3][1] = fmaf(av.w, bv.y, acc[3][1]);
            acc[3][2] = fmaf(av.w, bv.z, acc[3][2]);
            acc[3][3] = fmaf(av.w, bv.w, acc[3][3]);
        }
        __syncthreads();
    }
#pragma unroll
    for (int r = 0; r < 4; ++r)
#pragma unroll
        for (int c = 0; c < 4; ++c)
            out[(4 * ty + r) * 64 + 4 * tx + c] = acc[r][c];
}

__global__ void gram_reduce_kernel() {
    int o = blockIdx.x * blockDim.x + threadIdx.x;  // 8192
    const float* p = g_part + (o >> 12) * (KCHUNK * 4096) + (o & 4095);
    float s = 0.f;
#pragma unroll 8
    for (int c = 0; c < KCHUNK; ++c) s += p[c * 4096];
    g_c[o] = s;
}

// ============================================================
// Kernel 2/3: JS divergence
// ============================================================
__global__ void js_lse_kernel(const float* __restrict__ sr,
                              const float* __restrict__ hr) {
    int pos = blockIdx.x * blockDim.x + threadIdx.x;
    const float* ps = sr + pos;
    const float* ph = hr + pos;
    float m1 = -1e30f, s1 = 0.f, m2 = -1e30f, s2 = 0.f;
#pragma unroll 4
    for (int b = 0; b < BSZ; ++b) {
        float v = ps[(long)b * DFEAT];
        float nm = fmaxf(m1, v);
        s1 = s1 * exp2f((m1 - nm) * L2E) + exp2f((v - nm) * L2E);
        m1 = nm;
        float w = ph[(long)b * DFEAT];
        float nw = fmaxf(m2, w);
        s2 = s2 * exp2f((m2 - nw) * L2E) + exp2f((w - nw) * L2E);
        m2 = nw;
    }
    g_lse[pos]         = m1 + __logf(s1);
    g_lse[DFEAT + pos] = m2 + __logf(s2);
}

__device__ __forceinline__ void block_sum2(float& v1, float& v2, float* sred,
                                           int tid, int nwarp) {
    int lane = tid & 31, warp = tid >> 5;
#pragma unroll
    for (int o = 16; o; o >>= 1) {
        v1 += __shfl_xor_sync(0xffffffffu, v1, o);
        v2 += __shfl_xor_sync(0xffffffffu, v2, o);
    }
    if (!lane) { sred[warp] = v1; sred[32 + warp] = v2; }
    __syncthreads();
    if (!tid) {
        float a = 0.f, b = 0.f;
        for (int w = 0; w < nwarp; ++w) { a += sred[w]; b += sred[32 + w]; }
        v1 = a; v2 = b;
    }
}

__global__ void js_kl_kernel(const float* __restrict__ sr,
                             const float* __restrict__ hr) {
    __shared__ float sred[64];
    int tid = threadIdx.x;
    int pos = blockIdx.x * blockDim.x + tid;
    float l1 = g_lse[pos], l2 = g_lse[DFEAT + pos];
    float acc1 = 0.f, acc2 = 0.f;
#pragma unroll 4
    for (int b = 0; b < BSZ; ++b) {
        float lx = sr[(long)b * DFEAT + pos] - l1;
        float ly = hr[(long)b * DFEAT + pos] - l2;
        float px = exp2f(lx * L2E);
        float py = exp2f(ly * L2E);
        float mm = 0.5f * (px + py);
        float lm = __logf(mm);
        acc1 += mm * (lm - lx);
        acc2 += mm * (lm - ly);
    }
    block_sum2(acc1, acc2, sred, tid, 8);
    if (!tid) {
        g_js[blockIdx.x]         = acc1;
        g_js[JSBLK + blockIdx.x] = acc2;
    }
}

__global__ void adv_kernel(const float* __restrict__ d) {
    __shared__ float sred[64];
    int tid = threadIdx.x;
    float s = 0.f, dummy = 0.f;
    for (int i = tid; i < ADVN; i += 256) {
        float x = d[i];
        s += fmaxf(-x, 0.f) + log1pf(__expf(-fabsf(x)));
    }
    block_sum2(s, dummy, sred, tid, 8);
    if (!tid) g_adv = s;
}

// ============================================================
// Kernel 5: persistent single-block entropic GW
// Log-domain Sinkhorn, register-resident Mk, u32-redux row/col
// sums (fixed-point), hoisted warp-uniform work, tolerance exits
// ============================================================
#define P68 68
#define GW_SMEM_FLOATS (5 * 64 * P68 + 4 * 64 + 80)
#define GW_SMEM_BYTES  (GW_SMEM_FLOATS * 4 + 32)

__global__ __launch_bounds__(1024, 1) void gw_kernel() {
    extern __shared__ float sm[];
    float* c1  = sm;                 // 64*68
    float* c2  = c1 + 64 * P68;
    float* Tm  = c2 + 64 * P68;
    float* M1  = Tm + 64 * P68;
    float* Mk  = M1 + 64 * P68;      // row-major base-2 log kernel
    float* sa  = Mk + 64 * P68;      // potentials a (log2 units)
    float* sb  = sa + 64;
    float* r1  = sb + 64;
    float* r2  = r1 + 64;
    float* red = r2 + 64;            // 80 floats
    int*  cfl  = (int*)(red + 80);   // [0..2] inner flag rotation
    int*  ofl  = cfl + 3;            // [0..1] outer flag rotation

    int tid  = threadIdx.x;
    int lane = tid & 31, w = tid >> 5;
    int ii = tid >> 4, jq = (tid & 15) << 2;   // matmul mapping

    // ---- 1) load reduced grams ----
    for (int e = tid; e < 4096; e += 1024) {
        c1[(e >> 6) * P68 + (e & 63)] = g_c[e];
        c2[(e >> 6) * P68 + (e & 63)] = g_c[4096 + e];
    }
    __syncthreads();

    // ---- 2) distances + normalization ----
    if (tid < 64) r1[tid] = c1[tid * P68 + tid];
    else if (tid < 128) { int t = tid - 64; r2[t] = c2[t * P68 + t]; }
    __syncthreads();

    float lm1 = 0.f, lm2 = 0.f;
    for (int e = tid; e < 4096; e += 1024) {
        int i = e >> 6, j = e & 63;
        float d1 = sqrtf(fmaxf(r1[i] + r1[j] - 2.f * c1[i * P68 + j], 0.f));
        float d2 = sqrtf(fmaxf(r2[i] + r2[j] - 2.f * c2[i * P68 + j], 0.f));
        c1[i * P68 + j] = d1;
        c2[i * P68 + j] = d2;
        lm1 = fmaxf(lm1, d1);
        lm2 = fmaxf(lm2, d2);
    }
    warp_max2(lm1, lm2);
    if (!lane) { red[w] = lm1; red[32 + w] = lm2; }
    __syncthreads();
    if (!tid) {
        float a = red[0], b = red[32];
        for (int ww = 1; ww < 32; ++ww) { a = fmaxf(a, red[ww]); b = fmaxf(b, red[32 + ww]); }
        red[64] = 1.f / a;
        red[65] = 1.f / b;
        ofl[0] = 0; ofl[1] = 0;
    }
    __syncthreads();
    float inv1 = red[64], inv2 = red[65];
    for (int e = tid; e < 4096; e += 1024) {
        int i = e >> 6, j = e & 63;
        c1[i * P68 + j] *= inv1;
        c2[i * P68 + j] *= inv2;
        Tm[i * P68 + j] = 1.f / 4096.f;
    }
    __syncthreads();

    if (tid < 64) {
        float s = 0.f;
        for (int j = 0; j < 64; ++j) { float v = c1[tid * P68 + j]; s = fmaf(v, v, s); }
        r1[tid] = s * (1.f / 64.f);
    } else if (tid < 128) {
        int t = tid - 64;
        float s = 0.f;
        for (int j = 0; j < 64; ++j) { float v = c2[t * P68 + j]; s = fmaf(v, v, s); }
        r2[t] = s * (1.f / 64.f);
    } else if (tid < 192) {
        sb[tid - 128] = 0.f;        // warm-start seed for outer 0
    }
    __syncthreads();

    // ---- 3) outer mirror-descent ----
    for (int outer = 0; outer < OUTER; ++outer) {
        // M1 = T @ c2
        {
            float a0 = 0.f, a1 = 0.f, a2 = 0.f, a3 = 0.f;
#pragma unroll 8
            for (int k = 0; k < 64; ++k) {
                float tv = Tm[ii * P68 + k];
                float4 bv = *(const float4*)(c2 + k * P68 + jq);
                a0 = fmaf(tv, bv.x, a0);
                a1 = fmaf(tv, bv.y, a1);
                a2 = fmaf(tv, bv.z, a2);
                a3 = fmaf(tv, bv.w, a3);
            }
            *(float4*)(M1 + ii * P68 + jq) = make_float4(a0, a1, a2, a3);
        }
        __syncthreads();
        // Mk = (2 c1@M1 - constC) * KSCALE; outer-diff flag
        {
            float p0 = 0.f, p1 = 0.f, p2 = 0.f, p3 = 0.f;
#pragma unroll 8
            for (int k = 0; k < 64; ++k) {
                float av = c1[ii * P68 + k];
                float4 mv = *(const float4*)(M1 + k * P68 + jq);
                p0 = fmaf(av, mv.x, p0);
                p1 = fmaf(av, mv.y, p1);
                p2 = fmaf(av, mv.z, p2);
                p3 = fmaf(av, mv.w, p3);
            }
            float ri = r1[ii];
            float v0 = (2.f * p0 - ri - r2[jq + 0]) * KSCALE;
            float v1 = (2.f * p1 - ri - r2[jq + 1]) * KSCALE;
            float v2 = (2.f * p2 - ri - r2[jq + 2]) * KSCALE;
            float v3 = (2.f * p3 - ri - r2[jq + 3]) * KSCALE;
            float4 old = *(const float4*)(Mk + ii * P68 + jq);
            float dd = fmaxf(fmaxf(fabsf(old.x - v0), fabsf(old.y - v1)),
                             fmaxf(fabsf(old.z - v2), fabsf(old.w - v3)));
            if (dd > TH_MK) ofl[outer & 1] = 1;
            *(float4*)(Mk + ii * P68 + jq) = make_float4(v0, v1, v2, v3);
        }
        if (!tid) { cfl[0] = 0; cfl[1] = 0; cfl[2] = 0; }
        __syncthreads();

        // Outer tolerance fixed point: remaining outers ~identity on T.
        if (outer > 0 && ofl[outer & 1] == 0) break;
        if (!tid) ofl[(outer + 1) & 1] = 0;

        // ---- register-resident Mk slices ----
        float2 mr0 = *(const float2*)(Mk + w * P68 + 2 * lane);        // rows
        float2 mr1 = *(const float2*)(Mk + (w + 32) * P68 + 2 * lane);
        float mc00 = Mk[(2 * lane) * P68 + w];                          // cols
        float mc01 = Mk[(2 * lane + 1) * P68 + w];
        float mc10 = Mk[(2 * lane) * P68 + w + 32];
        float mc11 = Mk[(2 * lane + 1) * P68 + w + 32];

        // ---- a-update #1: max-stabilized over (Mk + b_warm) ----
        {
            float2 bv = *(const float2*)(sb + 2 * lane);
            float x0 = mr0.x + bv.x, x1 = mr0.y + bv.y;
            float y0 = mr1.x + bv.x, y1 = mr1.y + bv.y;
            float m0 = fmaxf(x0, x1);
            float m1 = fmaxf(y0, y1);
            warp_max2(m0, m1);
            float s0 = fex2(x0 - m0) + fex2(x1 - m0);
            float s1 = fex2(y0 - m1) + fex2(y1 - m1);
            warp_sum2(s0, s1);
            if ((lane & 15) == 0) {
                float mm = (lane < 16) ? m0 : m1;
                float ss = (lane < 16) ? s0 : s1;
                sa[(lane < 16) ? w : (w + 32)] = LOGP2 - (mm + flg2(ss));
            }
        }
        __syncthreads();

        // ---- preload warp-uniform values & precompute shifted exps ----
        float bo0 = sb[w], bo1 = sb[w + 32];
        float mb00 = mc00 + (bo0 + FXS), mb01 = mc01 + (bo0 + FXS);
        float mb10 = mc10 + (bo1 + FXS), mb11 = mc11 + (bo1 + FXS);
        float ao0, ao1;
        float maP0x, maP0y, maP1x, maP1y;

        // ---- pairs p = 1..199 {b,a}: redux-u32 sums, windowed exit ----
#pragma unroll 1
        for (int p = 1; p < INNER; ++p) {
            int wp = ((p - 1) >> 2) % 3;
            {   // b-phase: columns w, w+32
                float2 av = *(const float2*)(sa + 2 * lane);
                float s0 = fex2(mb00 + av.x) + fex2(mb01 + av.y);
                float s1 = fex2(mb10 + av.x) + fex2(mb11 + av.y);
                unsigned u0 = redux_add_u32(f2u_rni(s0));
                unsigned u1 = redux_add_u32(f2u_rni(s1));
                // prefetch for a-phase (sa stable during b-phase)
                ao0 = sa[w]; ao1 = sa[w + 32];
                maP0x = mr0.x + (ao0 + FXS); maP0y = mr0.y + (ao0 + FXS);
                maP1x = mr1.x + (ao1 + FXS); maP1y = mr1.y + (ao1 + FXS);
                if ((lane & 15) == 0) {
                    unsigned uu = (lane < 16) ? u0 : u1;
                    uu = (uu == 0u) ? 1u : uu;
                    float d = (LOGP2 + FXS) - flg2(u2f(uu));
                    float bo = (lane < 16) ? bo0 : bo1;
                    sb[(lane < 16) ? w : (w + 32)] = bo + d;
                    if (fabsf(d) > TH_IN) cfl[wp] = 1;
                }
            }
            __syncthreads();
            {   // a-phase: rows w, w+32
                float2 bv = *(const float2*)(sb + 2 * lane);
                float s0 = fex2(maP0x + bv.x) + fex2(maP0y + bv.y);
                float s1 = fex2(maP1x + bv.x) + fex2(maP1y + bv.y);
                unsigned u0 = redux_add_u32(f2u_rni(s0));
                unsigned u1 = redux_add_u32(f2u_rni(s1));
                // prefetch for next b-phase (sb stable during a-phase)
                bo0 = sb[w]; bo1 = sb[w + 32];
                mb00 = mc00 + (bo0 + FXS); mb01 = mc01 + (bo0 + FXS);
                mb10 = mc10 + (bo1 + FXS); mb11 = mc11 + (bo1 + FXS);
                if ((lane & 15) == 0) {
                    unsigned uu = (lane < 16) ? u0 : u1;
                    uu = (uu == 0u) ? 1u : uu;
                    float d = (LOGP2 + FXS) - flg2(u2f(uu));
                    float ao = (lane < 16) ? ao0 : ao1;
                    sa[(lane < 16) ? w : (w + 32)] = ao + d;
                    if (fabsf(d) > TH_IN) cfl[wp] = 1;
                }
            }
            __syncthreads();
            if ((p & 3) == 0) {
                int m = p >> 2;
                if (cfl[(m - 1) % 3] == 0) break;   // window converged
                if (!tid) cfl[(m + 1) % 3] = 0;
            }
        }

        {   // final b-phase (exact fp32, like ref's 200th b-update)
            float b0 = sb[w], b1 = sb[w + 32];
            float2 av = *(const float2*)(sa + 2 * lane);
            float s0 = fex2(mc00 + av.x + b0) + fex2(mc01 + av.y + b0);
            float s1 = fex2(mc10 + av.x + b1) + fex2(mc11 + av.y + b1);
            warp_sum2(s0, s1);
            if ((lane & 15) == 0) {
                float ss = (lane < 16) ? s0 : s1;
                float bo = (lane < 16) ? b0 : b1;
                sb[(lane < 16) ? w : (w + 32)] = bo + (LOGP2 - flg2(ss));
            }
        }
        __syncthreads();

        // ---- T = 2^(a + Mk + b) from column registers ----
        {
            float b0 = sb[w], b1 = sb[w + 32];
            float2 av = *(const float2*)(sa + 2 * lane);
            Tm[(2 * lane) * P68 + w]          = fex2(mc00 + av.x + b0);
            Tm[(2 * lane + 1) * P68 + w]      = fex2(mc01 + av.y + b0);
            Tm[(2 * lane) * P68 + w + 32]     = fex2(mc10 + av.x + b1);
            Tm[(2 * lane + 1) * P68 + w + 32] = fex2(mc11 + av.y + b1);
        }
        __syncthreads();
    }

    // ---- 4) gw = sum(tens(T) * T) ----
    {
        float a0 = 0.f, a1 = 0.f, a2 = 0.f, a3 = 0.f;
#pragma unroll 8
        for (int k = 0; k < 64; ++k) {
            float tv = Tm[ii * P68 + k];
            float4 bv = *(const float4*)(c2 + k * P68 + jq);
            a0 = fmaf(tv, bv.x, a0);
            a1 = fmaf(tv, bv.y, a1);
            a2 = fmaf(tv, bv.z, a2);
            a3 = fmaf(tv, bv.w, a3);
        }
        *(float4*)(M1 + ii * P68 + jq) = make_float4(a0, a1, a2, a3);
    }
    __syncthreads();
    {
        float p0 = 0.f, p1 = 0.f, p2 = 0.f, p3 = 0.f;
#pragma unroll 8
        for (int k = 0; k < 64; ++k) {
            float av = c1[ii * P68 + k];
            float4 mv = *(const float4*)(M1 + k * P68 + jq);
            p0 = fmaf(av, mv.x, p0);
            p1 = fmaf(av, mv.y, p1);
            p2 = fmaf(av, mv.z, p2);
            p3 = fmaf(av, mv.w, p3);
        }
        float ri = r1[ii];
        float local =
            (ri + r2[jq + 0] - 2.f * p0) * Tm[ii * P68 + jq + 0] +
            (ri + r2[jq + 1] - 2.f * p1) * Tm[ii * P68 + jq + 1] +
            (ri + r2[jq + 2] - 2.f * p2) * Tm[ii * P68 + jq + 2] +
            (ri + r2[jq + 3] - 2.f * p3) * Tm[ii * P68 + jq + 3];
        float dummy = 0.f;
        warp_sum2(local, dummy);
        if (!lane) red[w] = local;
        __syncthreads();
        if (!tid) {
            float s = 0.f;
            for (int ww = 0; ww < 32; ++ww) s += red[ww];
            g_gw = s;
        }
    }
}

// ============================================================
// Kernel 6: final combine
// ============================================================
__global__ void final_kernel(float* __restrict__ out) {
    __shared__ float sred[64];
    int tid = threadIdx.x;
    float s1 = 0.f, s2 = 0.f;
    for (int i = tid; i < JSBLK; i += 256) {
        s1 += g_js[i];
        s2 += g_js[JSBLK + i];
    }
    block_sum2(s1, s2, sred, tid, 8);
    if (!tid) {
        float js  = 0.5f * (s1 + s2) * (1.f / 64.f);
        float adv = g_adv * (1.f / (float)ADVN);
        float gw  = g_gw;
        float mx = fmaxf(gw, fmaxf(js, adv));
        float w0 = expf((gw - mx) * 10.f);
        float w1 = expf((js - mx) * 10.f);
        float w2 = expf((adv - mx) * 10.f);
        float den = w0 + w1 + w2;
        out[0] = (gw * w0 + js * w1 + adv * w2) / den;
    }
}

// ============================================================
extern "C" void kernel_launch(void* const* d_in, const int* in_sizes, int n_in,
                              void* d_out, int out_size) {
    const float* big[3] = {nullptr, nullptr, nullptr};
    const float* df = nullptr;
    int nb = 0;
    for (int i = 0; i < n_in; ++i) {
        if (in_sizes[i] == ADVN) df = (const float*)d_in[i];
        else if (nb < 3) big[nb++] = (const float*)d_in[i];
    }
    const float* lr = big[0];
    const float* sr = big[1];
    const float* hr = big[2];
    float* out = (float*)d_out;
    (void)out_size;

    cudaFuncSetAttribute(gw_kernel, cudaFuncAttributeMaxDynamicSharedMemorySize,
                         GW_SMEM_BYTES);

    gram_kernel<<<dim3(KCHUNK, 2), 256>>>(lr, sr);
    gram_reduce_kernel<<<32, 256>>>();
    js_lse_kernel<<<JSBLK, 256>>>(sr, hr);
    js_kl_kernel<<<JSBLK, 256>>>(sr, hr);
    adv_kernel<<<1, 256>>>(df);
    gw_kernel<<<1, 1024, GW_SMEM_BYTES>>>();
    final_kernel<<<1, 256>>>(out);
}

// round 15
// speedup vs baseline: 1.3396x; 1.1961x over previous
#include <cuda_runtime.h>
#include <cuda_fp16.h>
#include <math.h>

#define BSZ      64
#define DFEAT    196608            // 3*256*256
#define KCHUNK   128
#define CHUNK    (DFEAT / KCHUNK)  // 1536
#define TK       128
#define NTILE    (CHUNK / TK)      // 12
#define JSBLK    768
#define ADVN     16384
#define OUTER    30
#define INNER    200
#define L2E      1.4426950408889634f
#define EPS_GW   0.0005f
#define KSCALE   (L2E / EPS_GW)
#define LOGP2    (-6.0f)           // log2(1/64)
#define TH_F16   4e-3f             // f16-loop exit: |d| in log2 units
#define TH_MK    8e-3f             // outer exit: |dMk| in z units
#define FXS      31.0f             // fixed-point scale exponent
#define SH16     16.0f             // f16 exp shift (terms <= 2^10 < f16 max)
#define CLAMP16  12.0f             // arg clamp: term <= 2^27, no u32 wrap
#define POLISH   2                 // exact fp32 pairs after f16 loop

// ---- device scratch ----
__device__ float g_part[2 * KCHUNK * 4096];
__device__ float g_c[2 * 4096];
__device__ float g_lse[2 * DFEAT];
__device__ float g_js[2 * JSBLK];
__device__ float g_adv;
__device__ float g_gw;

__device__ __forceinline__ float fex2(float x) {
    float r;
    asm("ex2.approx.ftz.f32 %0, %1;" : "=f"(r) : "f"(x));
    return r;
}
__device__ __forceinline__ float flg2(float x) {
    float r;
    asm("lg2.approx.f32 %0, %1;" : "=f"(r) : "f"(x));
    return r;
}
__device__ __forceinline__ unsigned f2u_rni(float x) {
    unsigned r;
    asm("cvt.rni.u32.f32 %0, %1;" : "=r"(r) : "f"(x));
    return r;
}
__device__ __forceinline__ float u2f(unsigned x) {
    float r;
    asm("cvt.rn.f32.u32 %0, %1;" : "=f"(r) : "r"(x));
    return r;
}
__device__ __forceinline__ unsigned redux_add_u32(unsigned v) {
    unsigned r;
    asm("redux.sync.add.u32 %0, %1, 0xffffffff;" : "=r"(r) : "r"(v));
    return r;
}
__device__ __forceinline__ void warp_sum2(float& s0, float& s1) {
#pragma unroll
    for (int o = 16; o; o >>= 1) {
        float t0 = __shfl_xor_sync(0xffffffffu, s0, o);
        float t1 = __shfl_xor_sync(0xffffffffu, s1, o);
        s0 += t0;
        s1 += t1;
    }
}
__device__ __forceinline__ void warp_max2(float& s0, float& s1) {
#pragma unroll
    for (int o = 16; o; o >>= 1) {
        float t0 = __shfl_xor_sync(0xffffffffu, s0, o);
        float t1 = __shfl_xor_sync(0xffffffffu, s1, o);
        s0 = fmaxf(s0, t0);
        s1 = fmaxf(s1, t1);
    }
}

// ============================================================
// Kernel 1: Gram partials  G = X X^T  (64x64), K-chunked
// ============================================================
__global__ __launch_bounds__(256) void gram_kernel(const float* __restrict__ lr,
                                                   const float* __restrict__ sr) {
    __shared__ float tile2[TK][68];
    const float* X = blockIdx.y ? sr : lr;
    float* out = g_part + (blockIdx.y * KCHUNK + blockIdx.x) * 4096;

    int tid = threadIdx.x;
    int ty = tid >> 4, tx = tid & 15;
    float acc[4][4];
#pragma unroll
    for (int r = 0; r < 4; ++r)
#pragma unroll
        for (int c = 0; c < 4; ++c) acc[r][c] = 0.f;

    long k0base = (long)blockIdx.x * CHUNK;
    for (int t = 0; t < NTILE; ++t) {
        long k0 = k0base + (long)t * TK;
        for (int idx = tid; idx < 64 * TK; idx += 256) {
            int r = idx >> 7;
            int c = idx & 127;
            tile2[c][r] = X[(long)r * DFEAT + k0 + c];
        }
        __syncthreads();
#pragma unroll 4
        for (int k = 0; k < TK; ++k) {
            float4 av = *(const float4*)&tile2[k][4 * ty];
            float4 bv = *(const float4*)&tile2[k][4 * tx];
            acc[0][0] = fmaf(av.x, bv.x, acc[0][0]);
            acc[0][1] = fmaf(av.x, bv.y, acc[0][1]);
            acc[0][2] = fmaf(av.x, bv.z, acc[0][2]);
            acc[0][3] = fmaf(av.x, bv.w, acc[0][3]);
            acc[1][0] = fmaf(av.y, bv.x, acc[1][0]);
            acc[1][1] = fmaf(av.y, bv.y, acc[1][1]);
            acc[1][2] = fmaf(av.y, bv.z, acc[1][2]);
            acc[1][3] = fmaf(av.y, bv.w, acc[1][3]);
            acc[2][0] = fmaf(av.z, bv.x, acc[2][0]);
            acc[2][1] = fmaf(av.z, bv.y, acc[2][1]);
            acc[2][2] = fmaf(av.z, bv.z, acc[2][2]);
            acc[2][3] = fmaf(av.z, bv.w, acc[2][3]);
            acc[3][0] = fmaf(av.w, bv.x, acc[3][0]);
            acc[3][1] = fmaf(av.w, bv.y, acc[3][1]);
            acc[3][2] = fmaf(av.w, bv.z, acc[3][2]);
            acc[3][3] = fmaf(av.w, bv.w, acc[3][3]);
        }
        __syncthreads();
    }
#pragma unroll
    for (int r = 0; r < 4; ++r)
#pragma unroll
        for (int c = 0; c < 4; ++c)
            out[(4 * ty + r) * 64 + 4 * tx + c] = acc[r][c];
}

__global__ void gram_reduce_kernel() {
    int o = blockIdx.x * blockDim.x + threadIdx.x;  // 8192
    const float* p = g_part + (o >> 12) * (KCHUNK * 4096) + (o & 4095);
    float s = 0.f;
#pragma unroll 8
    for (int c = 0; c < KCHUNK; ++c) s += p[c * 4096];
    g_c[o] = s;
}

// ============================================================
// Kernel 2/3: JS divergence
// ============================================================
__global__ void js_lse_kernel(const float* __restrict__ sr,
                              const float* __restrict__ hr) {
    int pos = blockIdx.x * blockDim.x + threadIdx.x;
    const float* ps = sr + pos;
    const float* ph = hr + pos;
    float m1 = -1e30f, s1 = 0.f, m2 = -1e30f, s2 = 0.f;
#pragma unroll 4
    for (int b = 0; b < BSZ; ++b) {
        float v = ps[(long)b * DFEAT];
        float nm = fmaxf(m1, v);
        s1 = s1 * exp2f((m1 - nm) * L2E) + exp2f((v - nm) * L2E);
        m1 = nm;
        float w = ph[(long)b * DFEAT];
        float nw = fmaxf(m2, w);
        s2 = s2 * exp2f((m2 - nw) * L2E) + exp2f((w - nw) * L2E);
        m2 = nw;
    }
    g_lse[pos]         = m1 + __logf(s1);
    g_lse[DFEAT + pos] = m2 + __logf(s2);
}

__device__ __forceinline__ void block_sum2(float& v1, float& v2, float* sred,
                                           int tid, int nwarp) {
    int lane = tid & 31, warp = tid >> 5;
#pragma unroll
    for (int o = 16; o; o >>= 1) {
        v1 += __shfl_xor_sync(0xffffffffu, v1, o);
        v2 += __shfl_xor_sync(0xffffffffu, v2, o);
    }
    if (!lane) { sred[warp] = v1; sred[32 + warp] = v2; }
    __syncthreads();
    if (!tid) {
        float a = 0.f, b = 0.f;
        for (int w = 0; w < nwarp; ++w) { a += sred[w]; b += sred[32 + w]; }
        v1 = a; v2 = b;
    }
}

__global__ void js_kl_kernel(const float* __restrict__ sr,
                             const float* __restrict__ hr) {
    __shared__ float sred[64];
    int tid = threadIdx.x;
    int pos = blockIdx.x * blockDim.x + tid;
    float l1 = g_lse[pos], l2 = g_lse[DFEAT + pos];
    float acc1 = 0.f, acc2 = 0.f;
#pragma unroll 4
    for (int b = 0; b < BSZ; ++b) {
        float lx = sr[(long)b * DFEAT + pos] - l1;
        float ly = hr[(long)b * DFEAT + pos] - l2;
        float px = exp2f(lx * L2E);
        float py = exp2f(ly * L2E);
        float mm = 0.5f * (px + py);
        float lm = __logf(mm);
        acc1 += mm * (lm - lx);
        acc2 += mm * (lm - ly);
    }
    block_sum2(acc1, acc2, sred, tid, 8);
    if (!tid) {
        g_js[blockIdx.x]         = acc1;
        g_js[JSBLK + blockIdx.x] = acc2;
    }
}

__global__ void adv_kernel(const float* __restrict__ d) {
    __shared__ float sred[64];
    int tid = threadIdx.x;
    float s = 0.f, dummy = 0.f;
    for (int i = tid; i < ADVN; i += 256) {
        float x = d[i];
        s += fmaxf(-x, 0.f) + log1pf(__expf(-fabsf(x)));
    }
    block_sum2(s, dummy, sred, tid, 8);
    if (!tid) g_adv = s;
}

// ============================================================
// Kernel 5: persistent single-block entropic GW
// f16x2-exp Sinkhorn mainloop (halved MUFU), u32-redux sums,
// fp32 polish pairs + exact final b, tolerance exits
// ============================================================
#define P68 68
#define GW_SMEM_FLOATS (5 * 64 * P68 + 4 * 64 + 80)
#define GW_SMEM_BYTES  (GW_SMEM_FLOATS * 4 + 32)

__global__ __launch_bounds__(1024, 1) void gw_kernel() {
    extern __shared__ float sm[];
    float* c1  = sm;                 // 64*68
    float* c2  = c1 + 64 * P68;
    float* Tm  = c2 + 64 * P68;
    float* M1  = Tm + 64 * P68;
    float* Mk  = M1 + 64 * P68;      // row-major base-2 log kernel
    float* sa  = Mk + 64 * P68;      // potentials a (log2 units)
    float* sb  = sa + 64;
    float* r1  = sb + 64;
    float* r2  = r1 + 64;
    float* red = r2 + 64;            // 80 floats
    int*  cfl  = (int*)(red + 80);   // [0..2] inner flag rotation
    int*  ofl  = cfl + 3;            // [0..1] outer flag rotation

    int tid  = threadIdx.x;
    int lane = tid & 31, w = tid >> 5;
    int ii = tid >> 4, jq = (tid & 15) << 2;   // matmul mapping

    // ---- 1) load reduced grams ----
    for (int e = tid; e < 4096; e += 1024) {
        c1[(e >> 6) * P68 + (e & 63)] = g_c[e];
        c2[(e >> 6) * P68 + (e & 63)] = g_c[4096 + e];
    }
    __syncthreads();

    // ---- 2) distances + normalization ----
    if (tid < 64) r1[tid] = c1[tid * P68 + tid];
    else if (tid < 128) { int t = tid - 64; r2[t] = c2[t * P68 + t]; }
    __syncthreads();

    float lm1 = 0.f, lm2 = 0.f;
    for (int e = tid; e < 4096; e += 1024) {
        int i = e >> 6, j = e & 63;
        float d1 = sqrtf(fmaxf(r1[i] + r1[j] - 2.f * c1[i * P68 + j], 0.f));
        float d2 = sqrtf(fmaxf(r2[i] + r2[j] - 2.f * c2[i * P68 + j], 0.f));
        c1[i * P68 + j] = d1;
        c2[i * P68 + j] = d2;
        lm1 = fmaxf(lm1, d1);
        lm2 = fmaxf(lm2, d2);
    }
    warp_max2(lm1, lm2);
    if (!lane) { red[w] = lm1; red[32 + w] = lm2; }
    __syncthreads();
    if (!tid) {
        float a = red[0], b = red[32];
        for (int ww = 1; ww < 32; ++ww) { a = fmaxf(a, red[ww]); b = fmaxf(b, red[32 + ww]); }
        red[64] = 1.f / a;
        red[65] = 1.f / b;
        ofl[0] = 0; ofl[1] = 0;
    }
    __syncthreads();
    float inv1 = red[64], inv2 = red[65];
    for (int e = tid; e < 4096; e += 1024) {
        int i = e >> 6, j = e & 63;
        c1[i * P68 + j] *= inv1;
        c2[i * P68 + j] *= inv2;
        Tm[i * P68 + j] = 1.f / 4096.f;
    }
    __syncthreads();

    if (tid < 64) {
        float s = 0.f;
        for (int j = 0; j < 64; ++j) { float v = c1[tid * P68 + j]; s = fmaf(v, v, s); }
        r1[tid] = s * (1.f / 64.f);
    } else if (tid < 128) {
        int t = tid - 64;
        float s = 0.f;
        for (int j = 0; j < 64; ++j) { float v = c2[t * P68 + j]; s = fmaf(v, v, s); }
        r2[t] = s * (1.f / 64.f);
    } else if (tid < 192) {
        sb[tid - 128] = 0.f;        // warm-start seed for outer 0
    }
    __syncthreads();

    // ---- 3) outer mirror-descent ----
    for (int outer = 0; outer < OUTER; ++outer) {
        // M1 = T @ c2
        {
            float a0 = 0.f, a1 = 0.f, a2 = 0.f, a3 = 0.f;
#pragma unroll 8
            for (int k = 0; k < 64; ++k) {
                float tv = Tm[ii * P68 + k];
                float4 bv = *(const float4*)(c2 + k * P68 + jq);
                a0 = fmaf(tv, bv.x, a0);
                a1 = fmaf(tv, bv.y, a1);
                a2 = fmaf(tv, bv.z, a2);
                a3 = fmaf(tv, bv.w, a3);
            }
            *(float4*)(M1 + ii * P68 + jq) = make_float4(a0, a1, a2, a3);
        }
        __syncthreads();
        // Mk = (2 c1@M1 - constC) * KSCALE; outer-diff flag
        {
            float p0 = 0.f, p1 = 0.f, p2 = 0.f, p3 = 0.f;
#pragma unroll 8
            for (int k = 0; k < 64; ++k) {
                float av = c1[ii * P68 + k];
                float4 mv = *(const float4*)(M1 + k * P68 + jq);
                p0 = fmaf(av, mv.x, p0);
                p1 = fmaf(av, mv.y, p1);
                p2 = fmaf(av, mv.z, p2);
                p3 = fmaf(av, mv.w, p3);
            }
            float ri = r1[ii];
            float v0 = (2.f * p0 - ri - r2[jq + 0]) * KSCALE;
            float v1 = (2.f * p1 - ri - r2[jq + 1]) * KSCALE;
            float v2 = (2.f * p2 - ri - r2[jq + 2]) * KSCALE;
            float v3 = (2.f * p3 - ri - r2[jq + 3]) * KSCALE;
            float4 old = *(const float4*)(Mk + ii * P68 + jq);
            float dd = fmaxf(fmaxf(fabsf(old.x - v0), fabsf(old.y - v1)),
                             fmaxf(fabsf(old.z - v2), fabsf(old.w - v3)));
            if (dd > TH_MK) ofl[outer & 1] = 1;
            *(float4*)(Mk + ii * P68 + jq) = make_float4(v0, v1, v2, v3);
        }
        if (!tid) { cfl[0] = 0; cfl[1] = 0; cfl[2] = 0; }
        __syncthreads();

        // Outer tolerance fixed point: remaining outers ~identity on T.
        if (outer > 0 && ofl[outer & 1] == 0) break;
        if (!tid) ofl[(outer + 1) & 1] = 0;

        // ---- register-resident Mk slices ----
        float2 mr0 = *(const float2*)(Mk + w * P68 + 2 * lane);        // rows
        float2 mr1 = *(const float2*)(Mk + (w + 32) * P68 + 2 * lane);
        float mc00 = Mk[(2 * lane) * P68 + w];                          // cols
        float mc01 = Mk[(2 * lane + 1) * P68 + w];
        float mc10 = Mk[(2 * lane) * P68 + w + 32];
        float mc11 = Mk[(2 * lane + 1) * P68 + w + 32];

        // ---- a-update #1: exact fp32, max-stabilized over (Mk + b_warm) ----
        {
            float2 bv = *(const float2*)(sb + 2 * lane);
            float x0 = mr0.x + bv.x, x1 = mr0.y + bv.y;
            float y0 = mr1.x + bv.x, y1 = mr1.y + bv.y;
            float m0 = fmaxf(x0, x1);
            float m1 = fmaxf(y0, y1);
            warp_max2(m0, m1);
            float s0 = fex2(x0 - m0) + fex2(x1 - m0);
            float s1 = fex2(y0 - m1) + fex2(y1 - m1);
            warp_sum2(s0, s1);
            if ((lane & 15) == 0) {
                float mm = (lane < 16) ? m0 : m1;
                float ss = (lane < 16) ? s0 : s1;
                sa[(lane < 16) ? w : (w + 32)] = LOGP2 - (mm + flg2(ss));
            }
        }
        __syncthreads();

        // ---- preload warp-uniform values; f16 args carry +SH16 ----
        float bo0 = sb[w], bo1 = sb[w + 32];
        float mb00 = mc00 + (bo0 + SH16), mb01 = mc01 + (bo0 + SH16);
        float mb10 = mc10 + (bo1 + SH16), mb11 = mc11 + (bo1 + SH16);
        float ao0, ao1;
        float maP0x, maP0y, maP1x, maP1y;

        // ---- f16x2 mainloop: pairs p = 1..199 {b,a} ----
#pragma unroll 1
        for (int p = 1; p < INNER; ++p) {
            int wp = ((p - 1) >> 2) % 3;
            {   // b-phase: columns w, w+32
                float2 av = *(const float2*)(sa + 2 * lane);
                float t00 = fminf(mb00 + av.x, CLAMP16);
                float t01 = fminf(mb01 + av.y, CLAMP16);
                float t10 = fminf(mb10 + av.x, CLAMP16);
                float t11 = fminf(mb11 + av.y, CLAMP16);
                float2 f0 = __half22float2(h2exp2(__floats2half2_rn(t00, t01)));
                float2 f1 = __half22float2(h2exp2(__floats2half2_rn(t10, t11)));
                float s0 = fmaf(f0.x, 32768.f, f0.y * 32768.f);
                float s1 = fmaf(f1.x, 32768.f, f1.y * 32768.f);
                unsigned u0 = redux_add_u32(f2u_rni(s0));
                unsigned u1 = redux_add_u32(f2u_rni(s1));
                ao0 = sa[w]; ao1 = sa[w + 32];
                maP0x = mr0.x + (ao0 + SH16); maP0y = mr0.y + (ao0 + SH16);
                maP1x = mr1.x + (ao1 + SH16); maP1y = mr1.y + (ao1 + SH16);
                if ((lane & 15) == 0) {
                    unsigned uu = (lane < 16) ? u0 : u1;
                    uu = (uu == 0u) ? 1u : uu;
                    float d = (LOGP2 + FXS) - flg2(u2f(uu));
                    float bo = (lane < 16) ? bo0 : bo1;
                    sb[(lane < 16) ? w : (w + 32)] = bo + d;
                    if (fabsf(d) > TH_F16) cfl[wp] = 1;
                }
            }
            __syncthreads();
            {   // a-phase: rows w, w+32
                float2 bv = *(const float2*)(sb + 2 * lane);
                float t00 = fminf(maP0x + bv.x, CLAMP16);
                float t01 = fminf(maP0y + bv.y, CLAMP16);
                float t10 = fminf(maP1x + bv.x, CLAMP16);
                float t11 = fminf(maP1y + bv.y, CLAMP16);
                float2 f0 = __half22float2(h2exp2(__floats2half2_rn(t00, t01)));
                float2 f1 = __half22float2(h2exp2(__floats2half2_rn(t10, t11)));
                float s0 = fmaf(f0.x, 32768.f, f0.y * 32768.f);
                float s1 = fmaf(f1.x, 32768.f, f1.y * 32768.f);
                unsigned u0 = redux_add_u32(f2u_rni(s0));
                unsigned u1 = redux_add_u32(f2u_rni(s1));
                bo0 = sb[w]; bo1 = sb[w + 32];
                mb00 = mc00 + (bo0 + SH16); mb01 = mc01 + (bo0 + SH16);
                mb10 = mc10 + (bo1 + SH16); mb11 = mc11 + (bo1 + SH16);
                if ((lane & 15) == 0) {
                    unsigned uu = (lane < 16) ? u0 : u1;
                    uu = (uu == 0u) ? 1u : uu;
                    float d = (LOGP2 + FXS) - flg2(u2f(uu));
                    float ao = (lane < 16) ? ao0 : ao1;
                    sa[(lane < 16) ? w : (w + 32)] = ao + d;
                    if (fabsf(d) > TH_F16) cfl[wp] = 1;
                }
            }
            __syncthreads();
            if ((p & 3) == 0) {
                int m = p >> 2;
                if (cfl[(m - 1) % 3] == 0) break;   // window converged
                if (!tid) cfl[(m + 1) % 3] = 0;
            }
        }

        // ---- exact fp32 polish pairs (scrub f16 bias) ----
#pragma unroll 1
        for (int pp = 0; pp < POLISH; ++pp) {
            {   // b-phase
                float b0 = sb[w], b1 = sb[w + 32];
                float2 av = *(const float2*)(sa + 2 * lane);
                float s0 = fex2(mc00 + av.x + (b0 + FXS)) +
                           fex2(mc01 + av.y + (b0 + FXS));
                float s1 = fex2(mc10 + av.x + (b1 + FXS)) +
                           fex2(mc11 + av.y + (b1 + FXS));
                unsigned u0 = redux_add_u32(f2u_rni(s0));
                unsigned u1 = redux_add_u32(f2u_rni(s1));
                if ((lane & 15) == 0) {
                    unsigned uu = (lane < 16) ? u0 : u1;
                    uu = (uu == 0u) ? 1u : uu;
                    float d = (LOGP2 + FXS) - flg2(u2f(uu));
                    float bo = (lane < 16) ? b0 : b1;
                    sb[(lane < 16) ? w : (w + 32)] = bo + d;
                }
            }
            __syncthreads();
            {   // a-phase
                float a0 = sa[w], a1 = sa[w + 32];
                float2 bv = *(const float2*)(sb + 2 * lane);
                float s0 = fex2(mr0.x + a0 + (bv.x + FXS)) +
                           fex2(mr0.y + a0 + (bv.y + FXS));
                float s1 = fex2(mr1.x + a1 + (bv.x + FXS)) +
                           fex2(mr1.y + a1 + (bv.y + FXS));
                unsigned u0 = redux_add_u32(f2u_rni(s0));
                unsigned u1 = redux_add_u32(f2u_rni(s1));
                if ((lane & 15) == 0) {
                    unsigned uu = (lane < 16) ? u0 : u1;
                    uu = (uu == 0u) ? 1u : uu;
                    float d = (LOGP2 + FXS) - flg2(u2f(uu));
                    float ao = (lane < 16) ? a0 : a1;
                    sa[(lane < 16) ? w : (w + 32)] = ao + d;
                }
            }
            __syncthreads();
        }

        {   // final b-phase (exact fp32 butterfly, like ref's 200th)
            float b0 = sb[w], b1 = sb[w + 32];
            float2 av = *(const float2*)(sa + 2 * lane);
            float s0 = fex2(mc00 + av.x + b0) + fex2(mc01 + av.y + b0);
            float s1 = fex2(mc10 + av.x + b1) + fex2(mc11 + av.y + b1);
            warp_sum2(s0, s1);
            if ((lane & 15) == 0) {
                float ss = (lane < 16) ? s0 : s1;
                float bo = (lane < 16) ? b0 : b1;
                sb[(lane < 16) ? w : (w + 32)] = bo + (LOGP2 - flg2(ss));
            }
        }
        __syncthreads();

        // ---- T = 2^(a + Mk + b) from column registers ----
        {
            float b0 = sb[w], b1 = sb[w + 32];
            float2 av = *(const float2*)(sa + 2 * lane);
            Tm[(2 * lane) * P68 + w]          = fex2(mc00 + av.x + b0);
            Tm[(2 * lane + 1) * P68 + w]      = fex2(mc01 + av.y + b0);
            Tm[(2 * lane) * P68 + w + 32]     = fex2(mc10 + av.x + b1);
            Tm[(2 * lane + 1) * P68 + w + 32] = fex2(mc11 + av.y + b1);
        }
        __syncthreads();
    }

    // ---- 4) gw = sum(tens(T) * T) ----
    {
        float a0 = 0.f, a1 = 0.f, a2 = 0.f, a3 = 0.f;
#pragma unroll 8
        for (int k = 0; k < 64; ++k) {
            float tv = Tm[ii * P68 + k];
            float4 bv = *(const float4*)(c2 + k * P68 + jq);
            a0 = fmaf(tv, bv.x, a0);
            a1 = fmaf(tv, bv.y, a1);
            a2 = fmaf(tv, bv.z, a2);
            a3 = fmaf(tv, bv.w, a3);
        }
        *(float4*)(M1 + ii * P68 + jq) = make_float4(a0, a1, a2, a3);
    }
    __syncthreads();
    {
        float p0 = 0.f, p1 = 0.f, p2 = 0.f, p3 = 0.f;
#pragma unroll 8
        for (int k = 0; k < 64; ++k) {
            float av = c1[ii * P68 + k];
            float4 mv = *(const float4*)(M1 + k * P68 + jq);
            p0 = fmaf(av, mv.x, p0);
            p1 = fmaf(av, mv.y, p1);
            p2 = fmaf(av, mv.z, p2);
            p3 = fmaf(av, mv.w, p3);
        }
        float ri = r1[ii];
        float local =
            (ri + r2[jq + 0] - 2.f * p0) * Tm[ii * P68 + jq + 0] +
            (ri + r2[jq + 1] - 2.f * p1) * Tm[ii * P68 + jq + 1] +
            (ri + r2[jq + 2] - 2.f * p2) * Tm[ii * P68 + jq + 2] +
            (ri + r2[jq + 3] - 2.f * p3) * Tm[ii * P68 + jq + 3];
        float dummy = 0.f;
        warp_sum2(local, dummy);
        if (!lane) red[w] = local;
        __syncthreads();
        if (!tid) {
            float s = 0.f;
            for (int ww = 0; ww < 32; ++ww) s += red[ww];
            g_gw = s;
        }
    }
}

// ============================================================
// Kernel 6: final combine
// ============================================================
__global__ void final_kernel(float* __restrict__ out) {
    __shared__ float sred[64];
    int tid = threadIdx.x;
    float s1 = 0.f, s2 = 0.f;
    for (int i = tid; i < JSBLK; i += 256) {
        s1 += g_js[i];
        s2 += g_js[JSBLK + i];
    }
    block_sum2(s1, s2, sred, tid, 8);
    if (!tid) {
        float js  = 0.5f * (s1 + s2) * (1.f / 64.f);
        float adv = g_adv * (1.f / (float)ADVN);
        float gw  = g_gw;
        float mx = fmaxf(gw, fmaxf(js, adv));
        float w0 = expf((gw - mx) * 10.f);
        float w1 = expf((js - mx) * 10.f);
        float w2 = expf((adv - mx) * 10.f);
        float den = w0 + w1 + w2;
        out[0] = (gw * w0 + js * w1 + adv * w2) / den;
    }
}

// ============================================================
extern "C" void kernel_launch(void* const* d_in, const int* in_sizes, int n_in,
                              void* d_out, int out_size) {
    const float* big[3] = {nullptr, nullptr, nullptr};
    const float* df = nullptr;
    int nb = 0;
    for (int i = 0; i < n_in; ++i) {
        if (in_sizes[i] == ADVN) df = (const float*)d_in[i];
        else if (nb < 3) big[nb++] = (const float*)d_in[i];
    }
    const float* lr = big[0];
    const float* sr = big[1];
    const float* hr = big[2];
    float* out = (float*)d_out;
    (void)out_size;

    cudaFuncSetAttribute(gw_kernel, cudaFuncAttributeMaxDynamicSharedMemorySize,
                         GW_SMEM_BYTES);

    gram_kernel<<<dim3(KCHUNK, 2), 256>>>(lr, sr);
    gram_reduce_kernel<<<32, 256>>>();
    js_lse_kernel<<<JSBLK, 256>>>(sr, hr);
    js_kl_kernel<<<JSBLK, 256>>>(sr, hr);
    adv_kernel<<<1, 256>>>(df);
    gw_kernel<<<1, 1024, GW_SMEM_BYTES>>>();
    final_kernel<<<1, 256>>>(out);
}

// round 17
// speedup vs baseline: 2.4899x; 1.8586x over previous
#include <cuda_runtime.h>
#include <cuda_fp16.h>
#include <math.h>

#define BSZ      64
#define DFEAT    196608            // 3*256*256
#define KCHUNK   128
#define CHUNK    (DFEAT / KCHUNK)  // 1536
#define TK       128
#define NTILE    (CHUNK / TK)      // 12
#define JSBLK    768
#define ADVN     16384
#define OUTER    30
#define INNER    200
#define L2E      1.4426950408889634f
#define EPS_GW   0.0005f
#define KSCALE   (L2E / EPS_GW)
#define LOGP2    (-6.0f)           // log2(1/64)
#define TH_F16   2e-2f             // f16-loop exit: above f16 dither floor
#define TH_MK    8e-3f             // outer exit: |dMk| in z units
#define FXS      31.0f             // fixed-point scale exponent
#define SH16     16.0f             // f16 exp shift (terms <= 2^10 < f16 max)
#define CLAMP16  12.0f             // arg clamp: term <= 2^27, no u32 wrap
#define POLISH   3                 // exact fp32 pairs after f16 loop

// ---- device scratch ----
__device__ float g_part[2 * KCHUNK * 4096];
__device__ float g_c[2 * 4096];
__device__ float g_lse[2 * DFEAT];
__device__ float g_js[2 * JSBLK];
__device__ float g_adv;
__device__ float g_gw;

__device__ __forceinline__ float fex2(float x) {
    float r;
    asm("ex2.approx.ftz.f32 %0, %1;" : "=f"(r) : "f"(x));
    return r;
}
__device__ __forceinline__ float flg2(float x) {
    float r;
    asm("lg2.approx.f32 %0, %1;" : "=f"(r) : "f"(x));
    return r;
}
__device__ __forceinline__ unsigned f2u_rni(float x) {
    unsigned r;
    asm("cvt.rni.u32.f32 %0, %1;" : "=r"(r) : "f"(x));
    return r;
}
__device__ __forceinline__ float u2f(unsigned x) {
    float r;
    asm("cvt.rn.f32.u32 %0, %1;" : "=f"(r) : "r"(x));
    return r;
}
__device__ __forceinline__ unsigned redux_add_u32(unsigned v) {
    unsigned r;
    asm("redux.sync.add.u32 %0, %1, 0xffffffff;" : "=r"(r) : "r"(v));
    return r;
}
__device__ __forceinline__ void warp_sum2(float& s0, float& s1) {
#pragma unroll
    for (int o = 16; o; o >>= 1) {
        float t0 = __shfl_xor_sync(0xffffffffu, s0, o);
        float t1 = __shfl_xor_sync(0xffffffffu, s1, o);
        s0 += t0;
        s1 += t1;
    }
}
__device__ __forceinline__ void warp_max2(float& s0, float& s1) {
#pragma unroll
    for (int o = 16; o; o >>= 1) {
        float t0 = __shfl_xor_sync(0xffffffffu, s0, o);
        float t1 = __shfl_xor_sync(0xffffffffu, s1, o);
        s0 = fmaxf(s0, t0);
        s1 = fmaxf(s1, t1);
    }
}

// ============================================================
// Kernel 1: Gram partials  G = X X^T  (64x64), K-chunked
// ============================================================
__global__ __launch_bounds__(256) void gram_kernel(const float* __restrict__ lr,
                                                   const float* __restrict__ sr) {
    __shared__ float tile2[TK][68];
    const float* X = blockIdx.y ? sr : lr;
    float* out = g_part + (blockIdx.y * KCHUNK + blockIdx.x) * 4096;

    int tid = threadIdx.x;
    int ty = tid >> 4, tx = tid & 15;
    float acc[4][4];
#pragma unroll
    for (int r = 0; r < 4; ++r)
#pragma unroll
        for (int c = 0; c < 4; ++c) acc[r][c] = 0.f;

    long k0base = (long)blockIdx.x * CHUNK;
    for (int t = 0; t < NTILE; ++t) {
        long k0 = k0base + (long)t * TK;
        for (int idx = tid; idx < 64 * TK; idx += 256) {
            int r = idx >> 7;
            int c = idx & 127;
            tile2[c][r] = X[(long)r * DFEAT + k0 + c];
        }
        __syncthreads();
#pragma unroll 4
        for (int k = 0; k < TK; ++k) {
            float4 av = *(const float4*)&tile2[k][4 * ty];
            float4 bv = *(const float4*)&tile2[k][4 * tx];
            acc[0][0] = fmaf(av.x, bv.x, acc[0][0]);
            acc[0][1] = fmaf(av.x, bv.y, acc[0][1]);
            acc[0][2] = fmaf(av.x, bv.z, acc[0][2]);
            acc[0][3] = fmaf(av.x, bv.w, acc[0][3]);
            acc[1][0] = fmaf(av.y, bv.x, acc[1][0]);
            acc[1][1] = fmaf(av.y, bv.y, acc[1][1]);
            acc[1][2] = fmaf(av.y, bv.z, acc[1][2]);
            acc[1][3] = fmaf(av.y, bv.w, acc[1][3]);
            acc[2][0] = fmaf(av.z, bv.x, acc[2][0]);
            acc[2][1] = fmaf(av.z, bv.y, acc[2][1]);
            acc[2][2] = fmaf(av.z, bv.z, acc[2][2]);
            acc[2][3] = fmaf(av.z, bv.w, acc[2][3]);
            acc[3][0] = fmaf(av.w, bv.x, acc[3][0]);
            acc[3][1] = fmaf(av.w, bv.y, acc[3][1]);
            acc[3][2] = fmaf(av.w, bv.z, acc[3][2]);
            acc[3][3] = fmaf(av.w, bv.w, acc[3][3]);
        }
        __syncthreads();
    }
#pragma unroll
    for (int r = 0; r < 4; ++r)
#pragma unroll
        for (int c = 0; c < 4; ++c)
            out[(4 * ty + r) * 64 + 4 * tx + c] = acc[r][c];
}

__global__ void gram_reduce_kernel() {
    int o = blockIdx.x * blockDim.x + threadIdx.x;  // 8192
    const float* p = g_part + (o >> 12) * (KCHUNK * 4096) + (o & 4095);
    float s = 0.f;
#pragma unroll 8
    for (int c = 0; c < KCHUNK; ++c) s += p[c * 4096];
    g_c[o] = s;
}

// ============================================================
// Kernel 2/3: JS divergence
// ============================================================
__global__ void js_lse_kernel(const float* __restrict__ sr,
                              const float* __restrict__ hr) {
    int pos = blockIdx.x * blockDim.x + threadIdx.x;
    const float* ps = sr + pos;
    const float* ph = hr + pos;
    float m1 = -1e30f, s1 = 0.f, m2 = -1e30f, s2 = 0.f;
#pragma unroll 4
    for (int b = 0; b < BSZ; ++b) {
        float v = ps[(long)b * DFEAT];
        float nm = fmaxf(m1, v);
        s1 = s1 * exp2f((m1 - nm) * L2E) + exp2f((v - nm) * L2E);
        m1 = nm;
        float w = ph[(long)b * DFEAT];
        float nw = fmaxf(m2, w);
        s2 = s2 * exp2f((m2 - nw) * L2E) + exp2f((w - nw) * L2E);
        m2 = nw;
    }
    g_lse[pos]         = m1 + __logf(s1);
    g_lse[DFEAT + pos] = m2 + __logf(s2);
}

__device__ __forceinline__ void block_sum2(float& v1, float& v2, float* sred,
                                           int tid, int nwarp) {
    int lane = tid & 31, warp = tid >> 5;
#pragma unroll
    for (int o = 16; o; o >>= 1) {
        v1 += __shfl_xor_sync(0xffffffffu, v1, o);
        v2 += __shfl_xor_sync(0xffffffffu, v2, o);
    }
    if (!lane) { sred[warp] = v1; sred[32 + warp] = v2; }
    __syncthreads();
    if (!tid) {
        float a = 0.f, b = 0.f;
        for (int w = 0; w < nwarp; ++w) { a += sred[w]; b += sred[32 + w]; }
        v1 = a; v2 = b;
    }
}

__global__ void js_kl_kernel(const float* __restrict__ sr,
                             const float* __restrict__ hr) {
    __shared__ float sred[64];
    int tid = threadIdx.x;
    int pos = blockIdx.x * blockDim.x + tid;
    float l1 = g_lse[pos], l2 = g_lse[DFEAT + pos];
    float acc1 = 0.f, acc2 = 0.f;
#pragma unroll 4
    for (int b = 0; b < BSZ; ++b) {
        float lx = sr[(long)b * DFEAT + pos] - l1;
        float ly = hr[(long)b * DFEAT + pos] - l2;
        float px = exp2f(lx * L2E);
        float py = exp2f(ly * L2E);
        float mm = 0.5f * (px + py);
        float lm = __logf(mm);
        acc1 += mm * (lm - lx);
        acc2 += mm * (lm - ly);
    }
    block_sum2(acc1, acc2, sred, tid, 8);
    if (!tid) {
        g_js[blockIdx.x]         = acc1;
        g_js[JSBLK + blockIdx.x] = acc2;
    }
}

__global__ void adv_kernel(const float* __restrict__ d) {
    __shared__ float sred[64];
    int tid = threadIdx.x;
    float s = 0.f, dummy = 0.f;
    for (int i = tid; i < ADVN; i += 256) {
        float x = d[i];
        s += fmaxf(-x, 0.f) + log1pf(__expf(-fabsf(x)));
    }
    block_sum2(s, dummy, sred, tid, 8);
    if (!tid) g_adv = s;
}

// ============================================================
// Kernel 5: persistent single-block entropic GW
// f16x2-exp Sinkhorn mainloop, u32-redux sums, recalibrated
// exit thresholds, fp32 polish pairs + exact final b
// ============================================================
#define P68 68
#define GW_SMEM_FLOATS (5 * 64 * P68 + 4 * 64 + 80)
#define GW_SMEM_BYTES  (GW_SMEM_FLOATS * 4 + 32)

__global__ __launch_bounds__(1024, 1) void gw_kernel() {
    extern __shared__ float sm[];
    float* c1  = sm;                 // 64*68
    float* c2  = c1 + 64 * P68;
    float* Tm  = c2 + 64 * P68;
    float* M1  = Tm + 64 * P68;
    float* Mk  = M1 + 64 * P68;      // row-major base-2 log kernel
    float* sa  = Mk + 64 * P68;      // potentials a (log2 units)
    float* sb  = sa + 64;
    float* r1  = sb + 64;
    float* r2  = r1 + 64;
    float* red = r2 + 64;            // 80 floats
    int*  cfl  = (int*)(red + 80);   // [0..2] inner flag rotation
    int*  ofl  = cfl + 3;            // [0..1] outer flag rotation

    int tid  = threadIdx.x;
    int lane = tid & 31, w = tid >> 5;
    int ii = tid >> 4, jq = (tid & 15) << 2;   // matmul mapping

    // ---- 1) load reduced grams ----
    for (int e = tid; e < 4096; e += 1024) {
        c1[(e >> 6) * P68 + (e & 63)] = g_c[e];
        c2[(e >> 6) * P68 + (e & 63)] = g_c[4096 + e];
    }
    __syncthreads();

    // ---- 2) distances + normalization ----
    if (tid < 64) r1[tid] = c1[tid * P68 + tid];
    else if (tid < 128) { int t = tid - 64; r2[t] = c2[t * P68 + t]; }
    __syncthreads();

    float lm1 = 0.f, lm2 = 0.f;
    for (int e = tid; e < 4096; e += 1024) {
        int i = e >> 6, j = e & 63;
        float d1 = sqrtf(fmaxf(r1[i] + r1[j] - 2.f * c1[i * P68 + j], 0.f));
        float d2 = sqrtf(fmaxf(r2[i] + r2[j] - 2.f * c2[i * P68 + j], 0.f));
        c1[i * P68 + j] = d1;
        c2[i * P68 + j] = d2;
        lm1 = fmaxf(lm1, d1);
        lm2 = fmaxf(lm2, d2);
    }
    warp_max2(lm1, lm2);
    if (!lane) { red[w] = lm1; red[32 + w] = lm2; }
    __syncthreads();
    if (!tid) {
        float a = red[0], b = red[32];
        for (int ww = 1; ww < 32; ++ww) { a = fmaxf(a, red[ww]); b = fmaxf(b, red[32 + ww]); }
        red[64] = 1.f / a;
        red[65] = 1.f / b;
        ofl[0] = 0; ofl[1] = 0;
    }
    __syncthreads();
    float inv1 = red[64], inv2 = red[65];
    for (int e = tid; e < 4096; e += 1024) {
        int i = e >> 6, j = e & 63;
        c1[i * P68 + j] *= inv1;
        c2[i * P68 + j] *= inv2;
        Tm[i * P68 + j] = 1.f / 4096.f;
    }
    __syncthreads();

    if (tid < 64) {
        float s = 0.f;
        for (int j = 0; j < 64; ++j) { float v = c1[tid * P68 + j]; s = fmaf(v, v, s); }
        r1[tid] = s * (1.f / 64.f);
    } else if (tid < 128) {
        int t = tid - 64;
        float s = 0.f;
        for (int j = 0; j < 64; ++j) { float v = c2[t * P68 + j]; s = fmaf(v, v, s); }
        r2[t] = s * (1.f / 64.f);
    } else if (tid < 192) {
        sb[tid - 128] = 0.f;        // warm-start seed for outer 0
    }
    __syncthreads();

    // ---- 3) outer mirror-descent ----
    for (int outer = 0; outer < OUTER; ++outer) {
        // M1 = T @ c2
        {
            float a0 = 0.f, a1 = 0.f, a2 = 0.f, a3 = 0.f;
#pragma unroll 8
            for (int k = 0; k < 64; ++k) {
                float tv = Tm[ii * P68 + k];
                float4 bv = *(const float4*)(c2 + k * P68 + jq);
                a0 = fmaf(tv, bv.x, a0);
                a1 = fmaf(tv, bv.y, a1);
                a2 = fmaf(tv, bv.z, a2);
                a3 = fmaf(tv, bv.w, a3);
            }
            *(float4*)(M1 + ii * P68 + jq) = make_float4(a0, a1, a2, a3);
        }
        __syncthreads();
        // Mk = (2 c1@M1 - constC) * KSCALE; outer-diff flag
        {
            float p0 = 0.f, p1 = 0.f, p2 = 0.f, p3 = 0.f;
#pragma unroll 8
            for (int k = 0; k < 64; ++k) {
                float av = c1[ii * P68 + k];
                float4 mv = *(const float4*)(M1 + k * P68 + jq);
                p0 = fmaf(av, mv.x, p0);
                p1 = fmaf(av, mv.y, p1);
                p2 = fmaf(av, mv.z, p2);
                p3 = fmaf(av, mv.w, p3);
            }
            float ri = r1[ii];
            float v0 = (2.f * p0 - ri - r2[jq + 0]) * KSCALE;
            float v1 = (2.f * p1 - ri - r2[jq + 1]) * KSCALE;
            float v2 = (2.f * p2 - ri - r2[jq + 2]) * KSCALE;
            float v3 = (2.f * p3 - ri - r2[jq + 3]) * KSCALE;
            float4 old = *(const float4*)(Mk + ii * P68 + jq);
            float dd = fmaxf(fmaxf(fabsf(old.x - v0), fabsf(old.y - v1)),
                             fmaxf(fabsf(old.z - v2), fabsf(old.w - v3)));
            if (dd > TH_MK) ofl[outer & 1] = 1;
            *(float4*)(Mk + ii * P68 + jq) = make_float4(v0, v1, v2, v3);
        }
        if (!tid) { cfl[0] = 0; cfl[1] = 0; cfl[2] = 0; }
        __syncthreads();

        // Outer tolerance fixed point: remaining outers ~identity on T.
        if (outer > 0 && ofl[outer & 1] == 0) break;
        if (!tid) ofl[(outer + 1) & 1] = 0;

        // ---- register-resident Mk slices ----
        float2 mr0 = *(const float2*)(Mk + w * P68 + 2 * lane);        // rows
        float2 mr1 = *(const float2*)(Mk + (w + 32) * P68 + 2 * lane);
        float mc00 = Mk[(2 * lane) * P68 + w];                          // cols
        float mc01 = Mk[(2 * lane + 1) * P68 + w];
        float mc10 = Mk[(2 * lane) * P68 + w + 32];
        float mc11 = Mk[(2 * lane + 1) * P68 + w + 32];

        // ---- a-update #1: exact fp32, max-stabilized over (Mk + b_warm) ----
        {
            float2 bv = *(const float2*)(sb + 2 * lane);
            float x0 = mr0.x + bv.x, x1 = mr0.y + bv.y;
            float y0 = mr1.x + bv.x, y1 = mr1.y + bv.y;
            float m0 = fmaxf(x0, x1);
            float m1 = fmaxf(y0, y1);
            warp_max2(m0, m1);
            float s0 = fex2(x0 - m0) + fex2(x1 - m0);
            float s1 = fex2(y0 - m1) + fex2(y1 - m1);
            warp_sum2(s0, s1);
            if ((lane & 15) == 0) {
                float mm = (lane < 16) ? m0 : m1;
                float ss = (lane < 16) ? s0 : s1;
                sa[(lane < 16) ? w : (w + 32)] = LOGP2 - (mm + flg2(ss));
            }
        }
        __syncthreads();

        // ---- preload warp-uniform values; f16 args carry +SH16 ----
        float bo0 = sb[w], bo1 = sb[w + 32];
        float mb00 = mc00 + (bo0 + SH16), mb01 = mc01 + (bo0 + SH16);
        float mb10 = mc10 + (bo1 + SH16), mb11 = mc11 + (bo1 + SH16);
        float ao0, ao1;
        float maP0x, maP0y, maP1x, maP1y;

        // ---- f16x2 mainloop: pairs p = 1..199 {b,a} ----
#pragma unroll 1
        for (int p = 1; p < INNER; ++p) {
            int wp = ((p - 1) >> 2) % 3;
            {   // b-phase: columns w, w+32
                float2 av = *(const float2*)(sa + 2 * lane);
                float t00 = fminf(mb00 + av.x, CLAMP16);
                float t01 = fminf(mb01 + av.y, CLAMP16);
                float t10 = fminf(mb10 + av.x, CLAMP16);
                float t11 = fminf(mb11 + av.y, CLAMP16);
                float2 f0 = __half22float2(h2exp2(__floats2half2_rn(t00, t01)));
                float2 f1 = __half22float2(h2exp2(__floats2half2_rn(t10, t11)));
                float s0 = fmaf(f0.x, 32768.f, f0.y * 32768.f);
                float s1 = fmaf(f1.x, 32768.f, f1.y * 32768.f);
                unsigned u0 = redux_add_u32(f2u_rni(s0));
                unsigned u1 = redux_add_u32(f2u_rni(s1));
                ao0 = sa[w]; ao1 = sa[w + 32];
                maP0x = mr0.x + (ao0 + SH16); maP0y = mr0.y + (ao0 + SH16);
                maP1x = mr1.x + (ao1 + SH16); maP1y = mr1.y + (ao1 + SH16);
                if ((lane & 15) == 0) {
                    unsigned uu = (lane < 16) ? u0 : u1;
                    uu = (uu == 0u) ? 1u : uu;
                    float d = (LOGP2 + FXS) - flg2(u2f(uu));
                    float bo = (lane < 16) ? bo0 : bo1;
                    sb[(lane < 16) ? w : (w + 32)] = bo + d;
                    if (fabsf(d) > TH_F16) cfl[wp] = 1;
                }
            }
            __syncthreads();
            {   // a-phase: rows w, w+32
                float2 bv = *(const float2*)(sb + 2 * lane);
                float t00 = fminf(maP0x + bv.x, CLAMP16);
                float t01 = fminf(maP0y + bv.y, CLAMP16);
                float t10 = fminf(maP1x + bv.x, CLAMP16);
                float t11 = fminf(maP1y + bv.y, CLAMP16);
                float2 f0 = __half22float2(h2exp2(__floats2half2_rn(t00, t01)));
                float2 f1 = __half22float2(h2exp2(__floats2half2_rn(t10, t11)));
                float s0 = fmaf(f0.x, 32768.f, f0.y * 32768.f);
                float s1 = fmaf(f1.x, 32768.f, f1.y * 32768.f);
                unsigned u0 = redux_add_u32(f2u_rni(s0));
                unsigned u1 = redux_add_u32(f2u_rni(s1));
                bo0 = sb[w]; bo1 = sb[w + 32];
                mb00 = mc00 + (bo0 + SH16); mb01 = mc01 + (bo0 + SH16);
                mb10 = mc10 + (bo1 + SH16); mb11 = mc11 + (bo1 + SH16);
                if ((lane & 15) == 0) {
                    unsigned uu = (lane < 16) ? u0 : u1;
                    uu = (uu == 0u) ? 1u : uu;
                    float d = (LOGP2 + FXS) - flg2(u2f(uu));
                    float ao = (lane < 16) ? ao0 : ao1;
                    sa[(lane < 16) ? w : (w + 32)] = ao + d;
                    if (fabsf(d) > TH_F16) cfl[wp] = 1;
                }
            }
            __syncthreads();
            if ((p & 3) == 0) {
                int m = p >> 2;
                if (cfl[(m - 1) % 3] == 0) break;   // window converged
                if (!tid) cfl[(m + 1) % 3] = 0;
            }
        }

        // ---- exact fp32 polish pairs (scrub f16 bias) ----
#pragma unroll 1
        for (int pp = 0; pp < POLISH; ++pp) {
            {   // b-phase
                float b0 = sb[w], b1 = sb[w + 32];
                float2 av = *(const float2*)(sa + 2 * lane);
                float s0 = fex2(mc00 + av.x + (b0 + FXS)) +
                           fex2(mc01 + av.y + (b0 + FXS));
                float s1 = fex2(mc10 + av.x + (b1 + FXS)) +
                           fex2(mc11 + av.y + (b1 + FXS));
                unsigned u0 = redux_add_u32(f2u_rni(s0));
                unsigned u1 = redux_add_u32(f2u_rni(s1));
                if ((lane & 15) == 0) {
                    unsigned uu = (lane < 16) ? u0 : u1;
                    uu = (uu == 0u) ? 1u : uu;
                    float d = (LOGP2 + FXS) - flg2(u2f(uu));
                    float bo = (lane < 16) ? b0 : b1;
                    sb[(lane < 16) ? w : (w + 32)] = bo + d;
                }
            }
            __syncthreads();
            {   // a-phase
                float a0 = sa[w], a1 = sa[w + 32];
                float2 bv = *(const float2*)(sb + 2 * lane);
                float s0 = fex2(mr0.x + a0 + (bv.x + FXS)) +
                           fex2(mr0.y + a0 + (bv.y + FXS));
                float s1 = fex2(mr1.x + a1 + (bv.x + FXS)) +
                           fex2(mr1.y + a1 + (bv.y + FXS));
                unsigned u0 = redux_add_u32(f2u_rni(s0));
                unsigned u1 = redux_add_u32(f2u_rni(s1));
                if ((lane & 15) == 0) {
                    unsigned uu = (lane < 16) ? u0 : u1;
                    uu = (uu == 0u) ? 1u : uu;
                    float d = (LOGP2 + FXS) - flg2(u2f(uu));
                    float ao = (lane < 16) ? a0 : a1;
                    sa[(lane < 16) ? w : (w + 32)] = ao + d;
                }
            }
            __syncthreads();
        }

        {   // final b-phase (exact fp32 butterfly, like ref's 200th)
            float b0 = sb[w], b1 = sb[w + 32];
            float2 av = *(const float2*)(sa + 2 * lane);
            float s0 = fex2(mc00 + av.x + b0) + fex2(mc01 + av.y + b0);
            float s1 = fex2(mc10 + av.x + b1) + fex2(mc11 + av.y + b1);
            warp_sum2(s0, s1);
            if ((lane & 15) == 0) {
                float ss = (lane < 16) ? s0 : s1;
                float bo = (lane < 16) ? b0 : b1;
                sb[(lane < 16) ? w : (w + 32)] = bo + (LOGP2 - flg2(ss));
            }
        }
        __syncthreads();

        // ---- T = 2^(a + Mk + b) from column registers ----
        {
            float b0 = sb[w], b1 = sb[w + 32];
            float2 av = *(const float2*)(sa + 2 * lane);
            Tm[(2 * lane) * P68 + w]          = fex2(mc00 + av.x + b0);
            Tm[(2 * lane + 1) * P68 + w]      = fex2(mc01 + av.y + b0);
            Tm[(2 * lane) * P68 + w + 32]     = fex2(mc10 + av.x + b1);
            Tm[(2 * lane + 1) * P68 + w + 32] = fex2(mc11 + av.y + b1);
        }
        __syncthreads();
    }

    // ---- 4) gw = sum(tens(T) * T) ----
    {
        float a0 = 0.f, a1 = 0.f, a2 = 0.f, a3 = 0.f;
#pragma unroll 8
        for (int k = 0; k < 64; ++k) {
            float tv = Tm[ii * P68 + k];
            float4 bv = *(const float4*)(c2 + k * P68 + jq);
            a0 = fmaf(tv, bv.x, a0);
            a1 = fmaf(tv, bv.y, a1);
            a2 = fmaf(tv, bv.z, a2);
            a3 = fmaf(tv, bv.w, a3);
        }
        *(float4*)(M1 + ii * P68 + jq) = make_float4(a0, a1, a2, a3);
    }
    __syncthreads();
    {
        float p0 = 0.f, p1 = 0.f, p2 = 0.f, p3 = 0.f;
#pragma unroll 8
        for (int k = 0; k < 64; ++k) {
            float av = c1[ii * P68 + k];
            float4 mv = *(const float4*)(M1 + k * P68 + jq);
            p0 = fmaf(av, mv.x, p0);
            p1 = fmaf(av, mv.y, p1);
            p2 = fmaf(av, mv.z, p2);
            p3 = fmaf(av, mv.w, p3);
        }
        float ri = r1[ii];
        float local =
            (ri + r2[jq + 0] - 2.f * p0) * Tm[ii * P68 + jq + 0] +
            (ri + r2[jq + 1] - 2.f * p1) * Tm[ii * P68 + jq + 1] +
            (ri + r2[jq + 2] - 2.f * p2) * Tm[ii * P68 + jq + 2] +
            (ri + r2[jq + 3] - 2.f * p3) * Tm[ii * P68 + jq + 3];
        float dummy = 0.f;
        warp_sum2(local, dummy);
        if (!lane) red[w] = local;
        __syncthreads();
        if (!tid) {
            float s = 0.f;
            for (int ww = 0; ww < 32; ++ww) s += red[ww];
            g_gw = s;
        }
    }
}

// ============================================================
// Kernel 6: final combine
// ============================================================
__global__ void final_kernel(float* __restrict__ out) {
    __shared__ float sred[64];
    int tid = threadIdx.x;
    float s1 = 0.f, s2 = 0.f;
    for (int i = tid; i < JSBLK; i += 256) {
        s1 += g_js[i];
        s2 += g_js[JSBLK + i];
    }
    block_sum2(s1, s2, sred, tid, 8);
    if (!tid) {
        float js  = 0.5f * (s1 + s2) * (1.f / 64.f);
        float adv = g_adv * (1.f / (float)ADVN);
        float gw  = g_gw;
        float mx = fmaxf(gw, fmaxf(js, adv));
        float w0 = expf((gw - mx) * 10.f);
        float w1 = expf((js - mx) * 10.f);
        float w2 = expf((adv - mx) * 10.f);
        float den = w0 + w1 + w2;
        out[0] = (gw * w0 + js * w1 + adv * w2) / den;
    }
}

// ============================================================
extern "C" void kernel_launch(void* const* d_in, const int* in_sizes, int n_in,
                              void* d_out, int out_size) {
    const float* big[3] = {nullptr, nullptr, nullptr};
    const float* df = nullptr;
    int nb = 0;
    for (int i = 0; i < n_in; ++i) {
        if (in_sizes[i] == ADVN) df = (const float*)d_in[i];
        else if (nb < 3) big[nb++] = (const float*)d_in[i];
    }
    const float* lr = big[0];
    const float* sr = big[1];
    const float* hr = big[2];
    float* out = (float*)d_out;
    (void)out_size;

    cudaFuncSetAttribute(gw_kernel, cudaFuncAttributeMaxDynamicSharedMemorySize,
                         GW_SMEM_BYTES);

    gram_kernel<<<dim3(KCHUNK, 2), 256>>>(lr, sr);
    gram_reduce_kernel<<<32, 256>>>();
    js_lse_kernel<<<JSBLK, 256>>>(sr, hr);
    js_kl_kernel<<<JSBLK, 256>>>(sr, hr);
    adv_kernel<<<1, 256>>>(df);
    gw_kernel<<<1, 1024, GW_SMEM_BYTES>>>();
    final_kernel<<<1, 256>>>(out);
}